// round 15
// baseline (speedup 1.0000x reference)
#include <cuda_runtime.h>
#include <cuda_bf16.h>
#include <mma.h>
#include <math.h>

using namespace nvcuda;
typedef __nv_bfloat16 bf16;

// ---------------- problem constants ----------------
#define BB   8
#define HH   8
#define TT   1024
#define DD   512
#define DHH  64
#define FFD  2048
#define BT   8192        // B*T
#define BHH  64          // B*H

// weight offsets in the packed bf16 weight buffer
#define OFF_VQKV 0LL
#define OFF_VOUT (3LL*DD*DD)
#define OFF_VW1  (OFF_VOUT + (long long)DD*DD)
#define OFF_VW2  (OFF_VW1 + (long long)DD*FFD)
#define OFF_LQKV (OFF_VW2 + (long long)FFD*DD)
#define OFF_LOUT (OFF_LQKV + 3LL*DD*DD)
#define OFF_LW1  (OFF_LOUT + (long long)DD*DD)
#define OFF_LW2  (OFF_LW1 + (long long)DD*FFD)
#define WBF_TOTAL (OFF_LW2 + (long long)FFD*DD)

// ---------------- device scratch ----------------
__device__ float g_qkv[2ll * BT * DD];                 // fp32 Q,K (layer 1 only)
__device__ float g_scores[(long long)BHH * TT * TT];   // fp32 scores/probs (layer 1)
__device__ float g_tmp[(long long)BT * DD];
__device__ float g_outv[(long long)BT * DD];
__device__ float g_outl[(long long)BT * DD];
__device__ float g_w[BB * TT];
__device__ float g_mm[BB * 2];
__device__ int   g_ids[BB * TT];
__device__ float g_wl[BB * TT];

__device__ bf16 g_wbf[WBF_TOTAL];
__device__ bf16 g_xbf[(long long)BT * DD];
__device__ bf16 g_qkvbf[3ll * BT * DD];
__device__ bf16 g_probsbf[(long long)BHH * TT * TT];   // bf16 scores->probs (both layers)
__device__ bf16 g_ctxbf[(long long)BT * DD];
__device__ bf16 g_tmpbf[(long long)BT * DD];
__device__ bf16 g_outvbf[(long long)BT * DD];
__device__ bf16 g_ffbf[(long long)BT * FFD];

// =====================================================================
// fp32 SGEMM NN 128x128x8, 256 thr, 8x8 microtile, register prefetch.
// Used ONLY for layer-1 Q,K projections (threshold-critical).
// =====================================================================
__global__ void __launch_bounds__(256) sgemm128(
    const float* __restrict__ A, int lda, long long sA,
    const float* __restrict__ Bm, int ldb, long long sB,
    float* __restrict__ C, int ldc, long long sC, int K)
{
    const int z = blockIdx.z;
    A  += (long long)z * sA;
    Bm += (long long)z * sB;
    C  += (long long)z * sC;

    const int m0 = blockIdx.y * 128, n0 = blockIdx.x * 128;

    __shared__ __align__(16) float As[8][128];
    __shared__ __align__(16) float Bs[8][132];

    const int tid = threadIdx.x;
    const int ty  = tid >> 4;          // 0..15
    const int tx  = tid & 15;          // 0..15

    const int arow = tid >> 1;          // 0..127
    const int acol = (tid & 1) << 2;    // 0 or 4
    const int brow = tid >> 5;          // 0..7
    const int bcol = (tid & 31) << 2;   // 0..124

    const float* Ag = A + (long long)(m0 + arow) * lda + acol;
    const float* Bg = Bm + (long long)brow * ldb + n0 + bcol;

    float4 pa = *(const float4*)Ag;
    float4 pb = *(const float4*)Bg;

    float acc[8][8];
#pragma unroll
    for (int i = 0; i < 8; i++)
#pragma unroll
        for (int j = 0; j < 8; j++) acc[i][j] = 0.f;

    for (int k0 = 0; k0 < K; k0 += 8) {
        As[acol + 0][arow] = pa.x;
        As[acol + 1][arow] = pa.y;
        As[acol + 2][arow] = pa.z;
        As[acol + 3][arow] = pa.w;
        *(float4*)&Bs[brow][bcol] = pb;
        __syncthreads();
        if (k0 + 8 < K) {
            pa = *(const float4*)(Ag + k0 + 8);
            pb = *(const float4*)(Bg + (long long)(k0 + 8) * ldb);
        }
#pragma unroll
        for (int kk = 0; kk < 8; kk++) {
            float4 a0 = *(const float4*)&As[kk][ty * 8];
            float4 a1 = *(const float4*)&As[kk][ty * 8 + 4];
            float4 b0 = *(const float4*)&Bs[kk][tx * 8];
            float4 b1 = *(const float4*)&Bs[kk][tx * 8 + 4];
            float a[8] = {a0.x,a0.y,a0.z,a0.w,a1.x,a1.y,a1.z,a1.w};
            float b[8] = {b0.x,b0.y,b0.z,b0.w,b1.x,b1.y,b1.z,b1.w};
#pragma unroll
            for (int i = 0; i < 8; i++)
#pragma unroll
                for (int j = 0; j < 8; j++)
                    acc[i][j] = fmaf(a[i], b[j], acc[i][j]);
        }
        __syncthreads();
    }

#pragma unroll
    for (int i = 0; i < 8; i++) {
        float* cp = C + (long long)(m0 + ty * 8 + i) * ldc + n0 + tx * 8;
        *(float4*)cp       = make_float4(acc[i][0], acc[i][1], acc[i][2], acc[i][3]);
        *(float4*)(cp + 4) = make_float4(acc[i][4], acc[i][5], acc[i][6], acc[i][7]);
    }
}

// =====================================================================
// fp32 NT attention scores (layer 1): S = 0.125 * Q @ K^T per (b,h)
// 128x128 tile, K=64 staged in smem as [k][m]/[k][n] in two 32-chunks.
// =====================================================================
__global__ void __launch_bounds__(256) attn_scores128(
    const float* __restrict__ Q, const float* __restrict__ Km, float* __restrict__ S)
{
    const int z = blockIdx.z;
    const int b = z >> 3, h = z & 7;
    const float* Ab = Q  + ((long long)b * TT) * DD + h * DHH;
    const float* Bb = Km + ((long long)b * TT) * DD + h * DHH;
    float* Cb = S + (long long)z * TT * TT;

    const int m0 = blockIdx.y * 128, n0 = blockIdx.x * 128;

    __shared__ __align__(16) float As[32][132];
    __shared__ __align__(16) float Bs[32][132];

    const int tid = threadIdx.x;
    const int ty  = tid >> 4;
    const int tx  = tid & 15;

    float acc[8][8];
#pragma unroll
    for (int i = 0; i < 8; i++)
#pragma unroll
        for (int j = 0; j < 8; j++) acc[i][j] = 0.f;

#pragma unroll
    for (int kc = 0; kc < DHH; kc += 32) {
        __syncthreads();
#pragma unroll
        for (int p = 0; p < 4; p++) {
            const int idx = p * 256 + tid;
            const int row = idx >> 3;
            const int c4  = (idx & 7) << 2;
            float4 va = *(const float4*)(Ab + (long long)(m0 + row) * DD + kc + c4);
            float4 vb = *(const float4*)(Bb + (long long)(n0 + row) * DD + kc + c4);
            As[c4 + 0][row] = va.x; As[c4 + 1][row] = va.y;
            As[c4 + 2][row] = va.z; As[c4 + 3][row] = va.w;
            Bs[c4 + 0][row] = vb.x; Bs[c4 + 1][row] = vb.y;
            Bs[c4 + 2][row] = vb.z; Bs[c4 + 3][row] = vb.w;
        }
        __syncthreads();
#pragma unroll
        for (int kk = 0; kk < 32; kk++) {
            float4 a0 = *(const float4*)&As[kk][ty * 8];
            float4 a1 = *(const float4*)&As[kk][ty * 8 + 4];
            float4 b0 = *(const float4*)&Bs[kk][tx * 8];
            float4 b1 = *(const float4*)&Bs[kk][tx * 8 + 4];
            float a[8] = {a0.x,a0.y,a0.z,a0.w,a1.x,a1.y,a1.z,a1.w};
            float b[8] = {b0.x,b0.y,b0.z,b0.w,b1.x,b1.y,b1.z,b1.w};
#pragma unroll
            for (int i = 0; i < 8; i++)
#pragma unroll
                for (int j = 0; j < 8; j++)
                    acc[i][j] = fmaf(a[i], b[j], acc[i][j]);
        }
    }

#pragma unroll
    for (int i = 0; i < 8; i++) {
        float* cp = Cb + (long long)(m0 + ty * 8 + i) * TT + n0 + tx * 8;
        *(float4*)cp       = make_float4(acc[i][0]*0.125f, acc[i][1]*0.125f, acc[i][2]*0.125f, acc[i][3]*0.125f);
        *(float4*)(cp + 4) = make_float4(acc[i][4]*0.125f, acc[i][5]*0.125f, acc[i][6]*0.125f, acc[i][7]*0.125f);
    }
}

// helper: warp writes one 16x16 float fragment as bf16 via smem staging
__device__ __forceinline__ void frag_to_bf16(
    float* stage, const wmma::fragment<wmma::accumulator,16,16,16,float>& f,
    bf16* gptr, int ldc, int lane, float scale)
{
    wmma::store_matrix_sync(stage, f, 16, wmma::mem_row_major);
    __syncwarp();
    const float* sp = stage + lane * 8;
    __nv_bfloat162 h[4];
#pragma unroll
    for (int e = 0; e < 4; e++) {
        h[e].x = __float2bfloat16(sp[e * 2]     * scale);
        h[e].y = __float2bfloat16(sp[e * 2 + 1] * scale);
    }
    bf16* gp = gptr + (long long)(lane >> 1) * ldc + (lane & 1) * 8;
    *(uint4*)gp = *(uint4*)h;
    __syncwarp();
}

// =====================================================================
// bf16 WMMA GEMM (NN): optional fp32 out C, optional bf16 out Cbf,
// optional fp32 residual Res, optional relu. 128x128x32 tile, 8 warps.
// =====================================================================
__global__ void __launch_bounds__(256) bgemm_nn(
    const bf16* __restrict__ A, int lda, long long sA,
    const bf16* __restrict__ Bm, int ldb, long long sB,
    float* __restrict__ C, bf16* __restrict__ Cbf, int ldc, long long sC,
    const float* __restrict__ Res, int K, int relu)
{
    const int z = blockIdx.z;
    A  += (long long)z * sA;
    Bm += (long long)z * sB;
    if (C)   C   += (long long)z * sC;
    if (Cbf) Cbf += (long long)z * sC;
    if (Res) Res += (long long)z * sC;

    const int m0 = blockIdx.y * 128, n0 = blockIdx.x * 128;

    __shared__ __align__(16) bf16 As[128][40];
    __shared__ __align__(16) bf16 Bs[32][136];
    __shared__ __align__(16) float stage[8][264];

    const int tid  = threadIdx.x;
    const int warp = tid >> 5;
    const int lane = tid & 31;
    const int wm   = warp & 1;
    const int wn   = warp >> 1;

    wmma::fragment<wmma::accumulator, 16, 16, 16, float> acc[4][2];
    if (Res) {
#pragma unroll
        for (int i = 0; i < 4; i++)
#pragma unroll
            for (int j = 0; j < 2; j++)
                wmma::load_matrix_sync(acc[i][j],
                    Res + (long long)(m0 + wm * 64 + i * 16) * ldc + n0 + wn * 32 + j * 16,
                    ldc, wmma::mem_row_major);
    } else {
#pragma unroll
        for (int i = 0; i < 4; i++)
#pragma unroll
            for (int j = 0; j < 2; j++)
                wmma::fill_fragment(acc[i][j], 0.f);
    }

    const int arow = tid >> 2,  acg = (tid & 3) * 8;
    const int brow = tid >> 4,  bcg = (tid & 15) * 8;

    for (int k0 = 0; k0 < K; k0 += 32) {
        uint4 a0 = *(const uint4*)(A + (long long)(m0 + arow)      * lda + k0 + acg);
        uint4 a1 = *(const uint4*)(A + (long long)(m0 + arow + 64) * lda + k0 + acg);
        uint4 b0 = *(const uint4*)(Bm + (long long)(k0 + brow)      * ldb + n0 + bcg);
        uint4 b1 = *(const uint4*)(Bm + (long long)(k0 + brow + 16) * ldb + n0 + bcg);
        __syncthreads();
        *(uint4*)&As[arow][acg]      = a0;
        *(uint4*)&As[arow + 64][acg] = a1;
        *(uint4*)&Bs[brow][bcg]      = b0;
        *(uint4*)&Bs[brow + 16][bcg] = b1;
        __syncthreads();
#pragma unroll
        for (int kk = 0; kk < 32; kk += 16) {
            wmma::fragment<wmma::matrix_a, 16, 16, 16, bf16, wmma::row_major> af[4];
            wmma::fragment<wmma::matrix_b, 16, 16, 16, bf16, wmma::row_major> bfr[2];
#pragma unroll
            for (int i = 0; i < 4; i++)
                wmma::load_matrix_sync(af[i], &As[wm * 64 + i * 16][kk], 40);
#pragma unroll
            for (int j = 0; j < 2; j++)
                wmma::load_matrix_sync(bfr[j], &Bs[kk][wn * 32 + j * 16], 136);
#pragma unroll
            for (int i = 0; i < 4; i++)
#pragma unroll
                for (int j = 0; j < 2; j++)
                    wmma::mma_sync(acc[i][j], af[i], bfr[j], acc[i][j]);
        }
    }

#pragma unroll
    for (int i = 0; i < 4; i++)
#pragma unroll
        for (int j = 0; j < 2; j++) {
            if (relu) {
#pragma unroll
                for (int e = 0; e < acc[i][j].num_elements; e++)
                    acc[i][j].x[e] = fmaxf(acc[i][j].x[e], 0.f);
            }
            const long long off = (long long)(m0 + wm * 64 + i * 16) * ldc + n0 + wn * 32 + j * 16;
            if (C)
                wmma::store_matrix_sync(C + off, acc[i][j], ldc, wmma::mem_row_major);
            if (Cbf)
                frag_to_bf16(&stage[warp][0], acc[i][j], Cbf + off, ldc, lane, 1.f);
        }
}

// =====================================================================
// bf16 WMMA scores (layer 2, NT): bf16 out = 0.125 * Q @ K^T
// =====================================================================
__global__ void __launch_bounds__(256) bscores(
    const bf16* __restrict__ Q, const bf16* __restrict__ Kv, bf16* __restrict__ S)
{
    const int z = blockIdx.z;
    const int b = z >> 3, h = z & 7;
    const bf16* Ab = Q  + ((long long)b * TT) * DD + h * DHH;
    const bf16* Bb = Kv + ((long long)b * TT) * DD + h * DHH;
    bf16* Cb = S + (long long)z * TT * TT;

    const int m0 = blockIdx.y * 128, n0 = blockIdx.x * 128;

    __shared__ __align__(16) bf16 As[128][40];
    __shared__ __align__(16) bf16 Ks[128][40];
    __shared__ __align__(16) float stage[8][264];

    const int tid  = threadIdx.x;
    const int warp = tid >> 5;
    const int lane = tid & 31;
    const int wm   = warp & 1;
    const int wn   = warp >> 1;

    wmma::fragment<wmma::accumulator, 16, 16, 16, float> acc[4][2];
#pragma unroll
    for (int i = 0; i < 4; i++)
#pragma unroll
        for (int j = 0; j < 2; j++)
            wmma::fill_fragment(acc[i][j], 0.f);

    const int arow = tid >> 2, acg = (tid & 3) * 8;

#pragma unroll
    for (int k0 = 0; k0 < DHH; k0 += 32) {
        uint4 a0 = *(const uint4*)(Ab + (long long)(m0 + arow)      * DD + k0 + acg);
        uint4 a1 = *(const uint4*)(Ab + (long long)(m0 + arow + 64) * DD + k0 + acg);
        uint4 b0 = *(const uint4*)(Bb + (long long)(n0 + arow)      * DD + k0 + acg);
        uint4 b1 = *(const uint4*)(Bb + (long long)(n0 + arow + 64) * DD + k0 + acg);
        __syncthreads();
        *(uint4*)&As[arow][acg]      = a0;
        *(uint4*)&As[arow + 64][acg] = a1;
        *(uint4*)&Ks[arow][acg]      = b0;
        *(uint4*)&Ks[arow + 64][acg] = b1;
        __syncthreads();
#pragma unroll
        for (int kk = 0; kk < 32; kk += 16) {
            wmma::fragment<wmma::matrix_a, 16, 16, 16, bf16, wmma::row_major> af[4];
            wmma::fragment<wmma::matrix_b, 16, 16, 16, bf16, wmma::col_major> bfr[2];
#pragma unroll
            for (int i = 0; i < 4; i++)
                wmma::load_matrix_sync(af[i], &As[wm * 64 + i * 16][kk], 40);
#pragma unroll
            for (int j = 0; j < 2; j++)
                wmma::load_matrix_sync(bfr[j], &Ks[wn * 32 + j * 16][kk], 40);
#pragma unroll
            for (int i = 0; i < 4; i++)
#pragma unroll
                for (int j = 0; j < 2; j++)
                    wmma::mma_sync(acc[i][j], af[i], bfr[j], acc[i][j]);
        }
    }

#pragma unroll
    for (int i = 0; i < 4; i++)
#pragma unroll
        for (int j = 0; j < 2; j++) {
            const long long off = (long long)(m0 + wm * 64 + i * 16) * TT + n0 + wn * 32 + j * 16;
            frag_to_bf16(&stage[warp][0], acc[i][j], Cb + off, TT, lane, 0.125f);
        }
}

// =====================================================================
// bf16 WMMA PV -> bf16 ctx. 128x64x32 tile, 8 warps (4M x 2N).
// =====================================================================
__global__ void __launch_bounds__(256) bpv(
    const bf16* __restrict__ P, const bf16* __restrict__ V, bf16* __restrict__ ctx)
{
    const int z = blockIdx.y;
    const int b = z >> 3, h = z & 7;
    const bf16* Ab = P + (long long)z * TT * TT;
    const bf16* Bb = V + ((long long)b * TT) * DD + h * DHH;
    bf16* Cb = ctx + ((long long)b * TT) * DD + h * DHH;

    const int m0 = blockIdx.x * 128;

    __shared__ __align__(16) bf16 As[128][40];
    __shared__ __align__(16) bf16 Bs[32][72];
    __shared__ __align__(16) float stage[8][264];

    const int tid  = threadIdx.x;
    const int warp = tid >> 5;
    const int lane = tid & 31;
    const int wm   = warp & 3;
    const int wn   = warp >> 2;

    wmma::fragment<wmma::accumulator, 16, 16, 16, float> acc[2][2];
#pragma unroll
    for (int i = 0; i < 2; i++)
#pragma unroll
        for (int j = 0; j < 2; j++)
            wmma::fill_fragment(acc[i][j], 0.f);

    const int arow = tid >> 2, acg = (tid & 3) * 8;
    const int brow = tid >> 3, bcg = (tid & 7) * 8;

    for (int k0 = 0; k0 < TT; k0 += 32) {
        uint4 a0 = *(const uint4*)(Ab + (long long)(m0 + arow)      * TT + k0 + acg);
        uint4 a1 = *(const uint4*)(Ab + (long long)(m0 + arow + 64) * TT + k0 + acg);
        uint4 b0 = *(const uint4*)(Bb + (long long)(k0 + brow) * DD + bcg);
        __syncthreads();
        *(uint4*)&As[arow][acg]      = a0;
        *(uint4*)&As[arow + 64][acg] = a1;
        *(uint4*)&Bs[brow][bcg]      = b0;
        __syncthreads();
#pragma unroll
        for (int kk = 0; kk < 32; kk += 16) {
            wmma::fragment<wmma::matrix_a, 16, 16, 16, bf16, wmma::row_major> af[2];
            wmma::fragment<wmma::matrix_b, 16, 16, 16, bf16, wmma::row_major> bfr[2];
#pragma unroll
            for (int i = 0; i < 2; i++)
                wmma::load_matrix_sync(af[i], &As[wm * 32 + i * 16][kk], 40);
#pragma unroll
            for (int j = 0; j < 2; j++)
                wmma::load_matrix_sync(bfr[j], &Bs[kk][wn * 32 + j * 16], 72);
#pragma unroll
            for (int i = 0; i < 2; i++)
#pragma unroll
                for (int j = 0; j < 2; j++)
                    wmma::mma_sync(acc[i][j], af[i], bfr[j], acc[i][j]);
        }
    }

#pragma unroll
    for (int i = 0; i < 2; i++)
#pragma unroll
        for (int j = 0; j < 2; j++) {
            const long long off = (long long)(m0 + wm * 32 + i * 16) * DD + wn * 32 + j * 16;
            frag_to_bf16(&stage[warp][0], acc[i][j], Cb + off, DD, lane, 1.f);
        }
}

// =====================================================================
// Layer-1 row softmax (fp32 in/out + bf16 probs out), no mask.
// =====================================================================
__global__ void __launch_bounds__(256) softmax_rows_k(float* __restrict__ S,
                                                      bf16* __restrict__ Pbf)
{
    const long long r = blockIdx.x;
    float* row = S + r * TT;
    bf16*  rbf = Pbf + r * TT;
    const int tid = threadIdx.x;

    __shared__ float sh[256];

    float v[4];
    float mx = -3.4e38f;
#pragma unroll
    for (int i = 0; i < 4; i++) {
        v[i] = row[tid + i * 256];
        mx = fmaxf(mx, v[i]);
    }
    sh[tid] = mx; __syncthreads();
    for (int s = 128; s > 0; s >>= 1) { if (tid < s) sh[tid] = fmaxf(sh[tid], sh[tid + s]); __syncthreads(); }
    mx = sh[0]; __syncthreads();

    float e[4];
    float sum = 0.f;
#pragma unroll
    for (int i = 0; i < 4; i++) { e[i] = expf(v[i] - mx); sum += e[i]; }
    sh[tid] = sum; __syncthreads();
    for (int s = 128; s > 0; s >>= 1) { if (tid < s) sh[tid] += sh[tid + s]; __syncthreads(); }
    const float inv = 1.f / sh[0];

#pragma unroll
    for (int i = 0; i < 4; i++) {
        float p = e[i] * inv;
        row[tid + i * 256] = p;
        rbf[tid + i * 256] = __float2bfloat16(p);
    }
}

// =====================================================================
// Layer-2 masked softmax, bf16 in-place (continuous path).
// =====================================================================
__global__ void __launch_bounds__(256) softmax2_bf(bf16* __restrict__ P,
                                                   const int* __restrict__ ids)
{
    const long long r = blockIdx.x;
    const int q  = (int)(r & (TT - 1));
    const int bh = (int)(r >> 10);
    const int b  = bh >> 3;
    bf16* row = P + r * TT;
    const int tid = threadIdx.x;

    __shared__ float sh[256];

    const float NEG = __int_as_float(0xff800000);
    const int idbase = b * TT;
    const int qid = ids[idbase + q];

    float v[4];
    float mx = -3.4e38f;
#pragma unroll
    for (int i = 0; i < 4; i++) {
        int k = tid + i * 256;
        float x = __bfloat162float(row[k]);
        if (ids[idbase + k] != qid) x = NEG;
        v[i] = x;
        mx = fmaxf(mx, x);
    }
    sh[tid] = mx; __syncthreads();
    for (int s = 128; s > 0; s >>= 1) { if (tid < s) sh[tid] = fmaxf(sh[tid], sh[tid + s]); __syncthreads(); }
    mx = sh[0]; __syncthreads();

    float e[4];
    float sum = 0.f;
#pragma unroll
    for (int i = 0; i < 4; i++) { e[i] = expf(v[i] - mx); sum += e[i]; }
    sh[tid] = sum; __syncthreads();
    for (int s = 128; s > 0; s >>= 1) { if (tid < s) sh[tid] += sh[tid + s]; __syncthreads(); }
    const float inv = 1.f / sh[0];

#pragma unroll
    for (int i = 0; i < 4; i++)
        row[tid + i * 256] = __float2bfloat16(e[i] * inv);
}

// fp32 column sum (double accum) — layer 1 (threshold-critical)
__global__ void __launch_bounds__(256) colsum_k(const float* __restrict__ P,
                                                float* __restrict__ w)
{
    const int b = blockIdx.x;
    const int k = blockIdx.y * 256 + threadIdx.x;
    const float* p = P + (long long)b * HH * TT * TT + k;
    double s0 = 0, s1 = 0, s2 = 0, s3 = 0;
    for (long long i = 0; i < (long long)HH * TT; i += 4) {
        s0 += (double)p[i * TT];
        s1 += (double)p[(i + 1) * TT];
        s2 += (double)p[(i + 2) * TT];
        s3 += (double)p[(i + 3) * TT];
    }
    w[b * TT + k] = (float)(((s0 + s1) + (s2 + s3)) * (1.0 / HH));
}

// bf16 column sum — layer 2 (continuous path)
__global__ void __launch_bounds__(256) colsum_bf(const bf16* __restrict__ P,
                                                 float* __restrict__ w)
{
    const int b = blockIdx.x;
    const int k = blockIdx.y * 256 + threadIdx.x;
    const bf16* p = P + (long long)b * HH * TT * TT + k;
    double s0 = 0, s1 = 0, s2 = 0, s3 = 0;
    for (long long i = 0; i < (long long)HH * TT; i += 4) {
        s0 += (double)__bfloat162float(p[i * TT]);
        s1 += (double)__bfloat162float(p[(i + 1) * TT]);
        s2 += (double)__bfloat162float(p[(i + 2) * TT]);
        s3 += (double)__bfloat162float(p[(i + 3) * TT]);
    }
    w[b * TT + k] = (float)(((s0 + s1) + (s2 + s3)) * (1.0 / HH));
}

__global__ void __launch_bounds__(256) minmax_k(const float* __restrict__ w,
                                                float* __restrict__ mm)
{
    const int b = blockIdx.x, tid = threadIdx.x;
    __shared__ float smn[256], smx[256];
    float mn = 3.4e38f, mx = -3.4e38f;
    for (int t = tid; t < TT; t += 256) {
        float x = w[b * TT + t];
        mn = fminf(mn, x); mx = fmaxf(mx, x);
    }
    smn[tid] = mn; smx[tid] = mx; __syncthreads();
    for (int s = 128; s > 0; s >>= 1) {
        if (tid < s) { smn[tid] = fminf(smn[tid], smn[tid + s]); smx[tid] = fmaxf(smx[tid], smx[tid + s]); }
        __syncthreads();
    }
    if (tid == 0) { mm[b * 2] = smn[0]; mm[b * 2 + 1] = smx[0]; }
}

__global__ void winscan_k(const float* __restrict__ w, const float* __restrict__ mm,
                          int* __restrict__ ids)
{
    const int b = threadIdx.x;
    if (b >= BB) return;
    const float mn  = mm[b * 2];
    const float den = mm[b * 2 + 1] - mn + 1e-8f;
    const float* wb = w + b * TT;
    int* idb = ids + b * TT;

    bool cur = ((wb[0] - mn) / den) >= 0.5f;
    int start = 0, wid = 0;
    idb[0] = 0;
    for (int t = 1; t < TT; t++) {
        bool wt = ((wb[t] - mn) / den) >= 0.5f;
        if (wt != cur) {
            cur = wt;
            if (start + 1 != t) { start = t; wid++; }
        }
        idb[t] = wid;
    }
}

__global__ void __launch_bounds__(256) softmax1d_k(const float* __restrict__ w,
                                                   float* __restrict__ wl)
{
    const int b = blockIdx.x, tid = threadIdx.x;
    __shared__ float sh[256];
    float v[4];
    float mx = -3.4e38f;
#pragma unroll
    for (int i = 0; i < 4; i++) { v[i] = w[b * TT + tid + i * 256]; mx = fmaxf(mx, v[i]); }
    sh[tid] = mx; __syncthreads();
    for (int s = 128; s > 0; s >>= 1) { if (tid < s) sh[tid] = fmaxf(sh[tid], sh[tid + s]); __syncthreads(); }
    mx = sh[0]; __syncthreads();
    float e[4], sum = 0.f;
#pragma unroll
    for (int i = 0; i < 4; i++) { e[i] = expf(v[i] - mx); sum += e[i]; }
    sh[tid] = sum; __syncthreads();
    for (int s = 128; s > 0; s >>= 1) { if (tid < s) sh[tid] += sh[tid + s]; __syncthreads(); }
    const float inv = 1.f / sh[0];
#pragma unroll
    for (int i = 0; i < 4; i++) wl[b * TT + tid + i * 256] = e[i] * inv;
}

// in-place LayerNorm over D=512 + optional bf16 dual write
__global__ void __launch_bounds__(256) ln_k(float* __restrict__ X, bf16* __restrict__ Xbf)
{
    const long long r = blockIdx.x;
    float* row = X + r * DD;
    const int tid = threadIdx.x;
    __shared__ float sh[256];

    float x0 = row[tid], x1 = row[tid + 256];
    sh[tid] = x0 + x1; __syncthreads();
    for (int s = 128; s > 0; s >>= 1) { if (tid < s) sh[tid] += sh[tid + s]; __syncthreads(); }
    const float mean = sh[0] * (1.f / DD);
    __syncthreads();

    const float d0 = x0 - mean, d1 = x1 - mean;
    sh[tid] = d0 * d0 + d1 * d1; __syncthreads();
    for (int s = 128; s > 0; s >>= 1) { if (tid < s) sh[tid] += sh[tid + s]; __syncthreads(); }
    const float var = sh[0] * (1.f / DD);
    const float rs = 1.f / sqrtf(var + 1e-5f);
    const float y0 = d0 * rs, y1 = d1 * rs;
    row[tid] = y0;
    row[tid + 256] = y1;
    if (Xbf) {
        Xbf[r * DD + tid]       = __float2bfloat16(y0);
        Xbf[r * DD + tid + 256] = __float2bfloat16(y1);
    }
}

// float -> bf16 conversion
__global__ void __launch_bounds__(256) f2bf_k(const float* __restrict__ src,
                                              bf16* __restrict__ dst, long long n)
{
    const long long i = ((long long)blockIdx.x * 256 + threadIdx.x) * 4;
    if (i >= n) return;
    float4 v = *(const float4*)(src + i);
    __nv_bfloat162 p0, p1;
    p0.x = __float2bfloat16(v.x); p0.y = __float2bfloat16(v.y);
    p1.x = __float2bfloat16(v.z); p1.y = __float2bfloat16(v.w);
    *(__nv_bfloat162*)(dst + i)     = p0;
    *(__nv_bfloat162*)(dst + i + 2) = p1;
}

// out[:, 0:T, :] = 0 ; out[:, T:2T, :] = x
__global__ void __launch_bounds__(256) outinit_k(const float* __restrict__ x,
                                                 float* __restrict__ out)
{
    const long long idx = (long long)blockIdx.x * 256 + threadIdx.x;
    const int d = (int)(idx & (DD - 1));
    const long long rb = idx >> 9;
    const int r = (int)(rb & (2 * TT - 1));
    const int b = (int)(rb >> 11);
    out[idx] = (r < TT) ? 0.f : x[((long long)b * TT + (r - TT)) * DD + d];
}

// segmented pooling
__global__ void __launch_bounds__(512) pool_k(const float* __restrict__ outl,
                                              const float* __restrict__ wl,
                                              const int* __restrict__ ids,
                                              float* __restrict__ out)
{
    const int b = blockIdx.x, d = threadIdx.x;
    __shared__ int   sids[TT];
    __shared__ float swl[TT];
    for (int t = d; t < TT; t += 512) {
        sids[t] = ids[b * TT + t];
        swl[t]  = wl[b * TT + t];
    }
    __syncthreads();

    const float* xb = outl + (long long)b * TT * DD + d;
    float acc = 0.f;
    for (int t0 = 0; t0 < TT; t0 += 16) {
        float vals[16];
#pragma unroll
        for (int u = 0; u < 16; u++) vals[u] = xb[(long long)(t0 + u) * DD];
#pragma unroll
        for (int u = 0; u < 16; u++) {
            const int t = t0 + u;
            acc = fmaf(vals[u], swl[t], acc);
            const int curid = sids[t];
            const bool flush = (t == TT - 1) || (sids[t + 1] != curid);
            if (flush) {
                out[((long long)b * 2 * TT + curid) * DD + d] = acc;
                acc = 0.f;
            }
        }
    }
}

__global__ void __launch_bounds__(256) mapping_k(const int* __restrict__ ids,
                                                 float* __restrict__ out2)
{
    const long long idx = (long long)blockIdx.x * 256 + threadIdx.x;
    const int j = (int)(idx & (TT - 1));
    const long long wb = idx >> 10;
    const int wrow = (int)(wb & (TT - 1));
    const int b = (int)(wb >> 10);
    out2[idx] = (ids[b * TT + j] == wrow) ? 1.f : 0.f;
}

// =====================================================================
// host
// =====================================================================
extern "C" void kernel_launch(void* const* d_in, const int* in_sizes, int n_in,
                              void* d_out, int out_size)
{
    (void)in_sizes; (void)n_in; (void)out_size;
    const float* x       = (const float*)d_in[0];
    const float* v_qkv_w = (const float*)d_in[1];
    const float* v_out_w = (const float*)d_in[2];
    const float* v_w1    = (const float*)d_in[3];
    const float* v_w2    = (const float*)d_in[4];
    const float* l_qkv_w = (const float*)d_in[5];
    const float* l_out_w = (const float*)d_in[6];
    const float* l_w1    = (const float*)d_in[7];
    const float* l_w2    = (const float*)d_in[8];
    float* out = (float*)d_out;

    float *qkv, *scores, *tmp, *outv, *outl, *w, *mm, *wl;
    int* ids;
    bf16 *wbf, *xbf, *qkvbf, *probsbf, *ctxbf, *tmpbf, *outvbf, *ffbf;
    cudaGetSymbolAddress((void**)&qkv,    g_qkv);
    cudaGetSymbolAddress((void**)&scores, g_scores);
    cudaGetSymbolAddress((void**)&tmp,    g_tmp);
    cudaGetSymbolAddress((void**)&outv,   g_outv);
    cudaGetSymbolAddress((void**)&outl,   g_outl);
    cudaGetSymbolAddress((void**)&w,      g_w);
    cudaGetSymbolAddress((void**)&mm,     g_mm);
    cudaGetSymbolAddress((void**)&ids,    g_ids);
    cudaGetSymbolAddress((void**)&wl,     g_wl);
    cudaGetSymbolAddress((void**)&wbf,    g_wbf);
    cudaGetSymbolAddress((void**)&xbf,    g_xbf);
    cudaGetSymbolAddress((void**)&qkvbf,  g_qkvbf);
    cudaGetSymbolAddress((void**)&probsbf,g_probsbf);
    cudaGetSymbolAddress((void**)&ctxbf,  g_ctxbf);
    cudaGetSymbolAddress((void**)&tmpbf,  g_tmpbf);
    cudaGetSymbolAddress((void**)&outvbf, g_outvbf);
    cudaGetSymbolAddress((void**)&ffbf,   g_ffbf);

    const dim3 blk(256);
    const long long sQKVw = (long long)DD * DD;
    const long long sQKVc = (long long)BT * DD;

    // ---- weight + input conversions (small) ----
    auto cvt = [&](const float* s, bf16* d, long long n) {
        f2bf_k<<<(unsigned)((n + 1023) / 1024), blk>>>(s, d, n);
    };
    cvt(v_qkv_w, wbf + OFF_VQKV, 3LL * DD * DD);
    cvt(v_out_w, wbf + OFF_VOUT, (long long)DD * DD);
    cvt(v_w1,    wbf + OFF_VW1,  (long long)DD * FFD);
    cvt(v_w2,    wbf + OFF_VW2,  (long long)FFD * DD);
    cvt(l_qkv_w, wbf + OFF_LQKV, 3LL * DD * DD);
    cvt(l_out_w, wbf + OFF_LOUT, (long long)DD * DD);
    cvt(l_w1,    wbf + OFF_LW1,  (long long)DD * FFD);
    cvt(l_w2,    wbf + OFF_LW2,  (long long)FFD * DD);
    cvt(x, xbf, sQKVc);

    // ---------------- layer 1 (vanilla) ----------------
    // Q,K in fp32 (threshold-critical)
    sgemm128<<<dim3(DD / 128, BT / 128, 2), blk>>>(x, DD, 0, v_qkv_w, DD, sQKVw,
                                                   qkv, DD, sQKVc, DD);
    // V in bf16 (bf16-only output)
    bgemm_nn<<<dim3(DD / 128, BT / 128, 1), blk>>>(xbf, DD, 0,
                                                   wbf + OFF_VQKV + 2 * sQKVw, DD, 0,
                                                   nullptr, qkvbf + 2 * sQKVc, DD, 0,
                                                   nullptr, DD, 0);
    attn_scores128<<<dim3(TT / 128, TT / 128, BHH), blk>>>(qkv, qkv + sQKVc, scores);
    softmax_rows_k<<<BHH * TT, blk>>>(scores, probsbf);
    colsum_k<<<dim3(BB, TT / 256), blk>>>(scores, w);
    minmax_k<<<BB, blk>>>(w, mm);
    winscan_k<<<1, 32>>>(w, mm, ids);
    bpv<<<dim3(TT / 128, BHH), blk>>>(probsbf, qkvbf + 2 * sQKVc, ctxbf);
    bgemm_nn<<<dim3(DD / 128, BT / 128, 1), blk>>>(ctxbf, DD, 0, wbf + OFF_VOUT, DD, 0,
                                                   tmp, nullptr, DD, 0, x, DD, 0);
    ln_k<<<BT, blk>>>(tmp, tmpbf);
    bgemm_nn<<<dim3(FFD / 128, BT / 128, 1), blk>>>(tmpbf, DD, 0, wbf + OFF_VW1, FFD, 0,
                                                    nullptr, ffbf, FFD, 0, nullptr, DD, 1);
    bgemm_nn<<<dim3(DD / 128, BT / 128, 1), blk>>>(ffbf, FFD, 0, wbf + OFF_VW2, DD, 0,
                                                   outv, nullptr, DD, 0, tmp, FFD, 0);
    ln_k<<<BT, blk>>>(outv, outvbf);

    // ---------------- layer 2 (windowed, bf16 throughout) ----------------
    bgemm_nn<<<dim3(DD / 128, BT / 128, 3), blk>>>(outvbf, DD, 0, wbf + OFF_LQKV, DD, sQKVw,
                                                   nullptr, qkvbf, DD, sQKVc,
                                                   nullptr, DD, 0);
    bscores<<<dim3(TT / 128, TT / 128, BHH), blk>>>(qkvbf, qkvbf + sQKVc, probsbf);
    softmax2_bf<<<BHH * TT, blk>>>(probsbf, ids);
    colsum_bf<<<dim3(BB, TT / 256), blk>>>(probsbf, w);
    softmax1d_k<<<BB, blk>>>(w, wl);
    bpv<<<dim3(TT / 128, BHH), blk>>>(probsbf, qkvbf + 2 * sQKVc, ctxbf);
    bgemm_nn<<<dim3(DD / 128, BT / 128, 1), blk>>>(ctxbf, DD, 0, wbf + OFF_LOUT, DD, 0,
                                                   tmp, nullptr, DD, 0, outv, DD, 0);
    ln_k<<<BT, blk>>>(tmp, tmpbf);
    bgemm_nn<<<dim3(FFD / 128, BT / 128, 1), blk>>>(tmpbf, DD, 0, wbf + OFF_LW1, FFD, 0,
                                                    nullptr, ffbf, FFD, 0, nullptr, DD, 1);
    bgemm_nn<<<dim3(DD / 128, BT / 128, 1), blk>>>(ffbf, FFD, 0, wbf + OFF_LW2, DD, 0,
                                                   outl, nullptr, DD, 0, tmp, FFD, 0);
    ln_k<<<BT, blk>>>(outl, nullptr);

    // ---------------- outputs ----------------
    const long long n1 = (long long)BB * 2 * TT * DD;
    outinit_k<<<(unsigned)(n1 / 256), blk>>>(x, out);
    pool_k<<<BB, 512>>>(outl, wl, ids, out);
    mapping_k<<<(unsigned)(((long long)BB * TT * TT) / 256), blk>>>(ids, out + n1);
}

// round 16
// speedup vs baseline: 1.0011x; 1.0011x over previous
#include <cuda_runtime.h>
#include <cuda_bf16.h>
#include <mma.h>
#include <math.h>

using namespace nvcuda;
typedef __nv_bfloat16 bf16;

// ---------------- problem constants ----------------
#define BB   8
#define HH   8
#define TT   1024
#define DD   512
#define DHH  64
#define FFD  2048
#define BT   8192        // B*T
#define BHH  64          // B*H

// weight offsets in the packed bf16 weight buffer
#define OFF_VQKV 0LL
#define OFF_VOUT (3LL*DD*DD)
#define OFF_VW1  (OFF_VOUT + (long long)DD*DD)
#define OFF_VW2  (OFF_VW1 + (long long)DD*FFD)
#define OFF_LQKV (OFF_VW2 + (long long)FFD*DD)
#define OFF_LOUT (OFF_LQKV + 3LL*DD*DD)
#define OFF_LW1  (OFF_LOUT + (long long)DD*DD)
#define OFF_LW2  (OFF_LW1 + (long long)DD*FFD)
#define WBF_TOTAL (OFF_LW2 + (long long)FFD*DD)

// ---------------- device scratch ----------------
__device__ float g_qkv[2ll * BT * DD];                 // fp32 Q,K (layer 1 only)
__device__ float g_scores[(long long)BHH * TT * TT];   // fp32 scores/probs (layer 1)
__device__ float g_tmp[(long long)BT * DD];
__device__ float g_outv[(long long)BT * DD];
__device__ float g_outl[(long long)BT * DD];
__device__ float g_w[BB * TT];
__device__ float g_mm[BB * 2];
__device__ int   g_ids[BB * TT];
__device__ float g_wl[BB * TT];

__device__ bf16 g_wbf[WBF_TOTAL];
__device__ bf16 g_xbf[(long long)BT * DD];
__device__ bf16 g_qkvbf[3ll * BT * DD];
__device__ bf16 g_probsbf[(long long)BHH * TT * TT];   // bf16 scores->probs (both layers)
__device__ bf16 g_ctxbf[(long long)BT * DD];
__device__ bf16 g_tmpbf[(long long)BT * DD];
__device__ bf16 g_outvbf[(long long)BT * DD];
__device__ bf16 g_ffbf[(long long)BT * FFD];

// =====================================================================
// fp32 SGEMM NN 128x128x8, 256 thr, 8x8 microtile, register prefetch.
// Used ONLY for layer-1 Q,K projections (threshold-critical).
// =====================================================================
__global__ void __launch_bounds__(256) sgemm128(
    const float* __restrict__ A, int lda, long long sA,
    const float* __restrict__ Bm, int ldb, long long sB,
    float* __restrict__ C, int ldc, long long sC, int K)
{
    const int z = blockIdx.z;
    A  += (long long)z * sA;
    Bm += (long long)z * sB;
    C  += (long long)z * sC;

    const int m0 = blockIdx.y * 128, n0 = blockIdx.x * 128;

    __shared__ __align__(16) float As[8][128];
    __shared__ __align__(16) float Bs[8][132];

    const int tid = threadIdx.x;
    const int ty  = tid >> 4;          // 0..15
    const int tx  = tid & 15;          // 0..15

    const int arow = tid >> 1;          // 0..127
    const int acol = (tid & 1) << 2;    // 0 or 4
    const int brow = tid >> 5;          // 0..7
    const int bcol = (tid & 31) << 2;   // 0..124

    const float* Ag = A + (long long)(m0 + arow) * lda + acol;
    const float* Bg = Bm + (long long)brow * ldb + n0 + bcol;

    float4 pa = *(const float4*)Ag;
    float4 pb = *(const float4*)Bg;

    float acc[8][8];
#pragma unroll
    for (int i = 0; i < 8; i++)
#pragma unroll
        for (int j = 0; j < 8; j++) acc[i][j] = 0.f;

    for (int k0 = 0; k0 < K; k0 += 8) {
        As[acol + 0][arow] = pa.x;
        As[acol + 1][arow] = pa.y;
        As[acol + 2][arow] = pa.z;
        As[acol + 3][arow] = pa.w;
        *(float4*)&Bs[brow][bcol] = pb;
        __syncthreads();
        if (k0 + 8 < K) {
            pa = *(const float4*)(Ag + k0 + 8);
            pb = *(const float4*)(Bg + (long long)(k0 + 8) * ldb);
        }
#pragma unroll
        for (int kk = 0; kk < 8; kk++) {
            float4 a0 = *(const float4*)&As[kk][ty * 8];
            float4 a1 = *(const float4*)&As[kk][ty * 8 + 4];
            float4 b0 = *(const float4*)&Bs[kk][tx * 8];
            float4 b1 = *(const float4*)&Bs[kk][tx * 8 + 4];
            float a[8] = {a0.x,a0.y,a0.z,a0.w,a1.x,a1.y,a1.z,a1.w};
            float b[8] = {b0.x,b0.y,b0.z,b0.w,b1.x,b1.y,b1.z,b1.w};
#pragma unroll
            for (int i = 0; i < 8; i++)
#pragma unroll
                for (int j = 0; j < 8; j++)
                    acc[i][j] = fmaf(a[i], b[j], acc[i][j]);
        }
        __syncthreads();
    }

#pragma unroll
    for (int i = 0; i < 8; i++) {
        float* cp = C + (long long)(m0 + ty * 8 + i) * ldc + n0 + tx * 8;
        *(float4*)cp       = make_float4(acc[i][0], acc[i][1], acc[i][2], acc[i][3]);
        *(float4*)(cp + 4) = make_float4(acc[i][4], acc[i][5], acc[i][6], acc[i][7]);
    }
}

// =====================================================================
// fp32 NT attention scores (layer 1): S = 0.125 * Q @ K^T per (b,h)
// 128x128 tile, K=64 staged in smem as [k][m]/[k][n] in two 32-chunks.
// =====================================================================
__global__ void __launch_bounds__(256) attn_scores128(
    const float* __restrict__ Q, const float* __restrict__ Km, float* __restrict__ S)
{
    const int z = blockIdx.z;
    const int b = z >> 3, h = z & 7;
    const float* Ab = Q  + ((long long)b * TT) * DD + h * DHH;
    const float* Bb = Km + ((long long)b * TT) * DD + h * DHH;
    float* Cb = S + (long long)z * TT * TT;

    const int m0 = blockIdx.y * 128, n0 = blockIdx.x * 128;

    __shared__ __align__(16) float As[32][132];
    __shared__ __align__(16) float Bs[32][132];

    const int tid = threadIdx.x;
    const int ty  = tid >> 4;
    const int tx  = tid & 15;

    float acc[8][8];
#pragma unroll
    for (int i = 0; i < 8; i++)
#pragma unroll
        for (int j = 0; j < 8; j++) acc[i][j] = 0.f;

#pragma unroll
    for (int kc = 0; kc < DHH; kc += 32) {
        __syncthreads();
#pragma unroll
        for (int p = 0; p < 4; p++) {
            const int idx = p * 256 + tid;
            const int row = idx >> 3;
            const int c4  = (idx & 7) << 2;
            float4 va = *(const float4*)(Ab + (long long)(m0 + row) * DD + kc + c4);
            float4 vb = *(const float4*)(Bb + (long long)(n0 + row) * DD + kc + c4);
            As[c4 + 0][row] = va.x; As[c4 + 1][row] = va.y;
            As[c4 + 2][row] = va.z; As[c4 + 3][row] = va.w;
            Bs[c4 + 0][row] = vb.x; Bs[c4 + 1][row] = vb.y;
            Bs[c4 + 2][row] = vb.z; Bs[c4 + 3][row] = vb.w;
        }
        __syncthreads();
#pragma unroll
        for (int kk = 0; kk < 32; kk++) {
            float4 a0 = *(const float4*)&As[kk][ty * 8];
            float4 a1 = *(const float4*)&As[kk][ty * 8 + 4];
            float4 b0 = *(const float4*)&Bs[kk][tx * 8];
            float4 b1 = *(const float4*)&Bs[kk][tx * 8 + 4];
            float a[8] = {a0.x,a0.y,a0.z,a0.w,a1.x,a1.y,a1.z,a1.w};
            float b[8] = {b0.x,b0.y,b0.z,b0.w,b1.x,b1.y,b1.z,b1.w};
#pragma unroll
            for (int i = 0; i < 8; i++)
#pragma unroll
                for (int j = 0; j < 8; j++)
                    acc[i][j] = fmaf(a[i], b[j], acc[i][j]);
        }
    }

#pragma unroll
    for (int i = 0; i < 8; i++) {
        float* cp = Cb + (long long)(m0 + ty * 8 + i) * TT + n0 + tx * 8;
        *(float4*)cp       = make_float4(acc[i][0]*0.125f, acc[i][1]*0.125f, acc[i][2]*0.125f, acc[i][3]*0.125f);
        *(float4*)(cp + 4) = make_float4(acc[i][4]*0.125f, acc[i][5]*0.125f, acc[i][6]*0.125f, acc[i][7]*0.125f);
    }
}

// helper: warp writes one 16x16 float fragment as bf16 via smem staging
__device__ __forceinline__ void frag_to_bf16(
    float* stage, const wmma::fragment<wmma::accumulator,16,16,16,float>& f,
    bf16* gptr, int ldc, int lane, float scale)
{
    wmma::store_matrix_sync(stage, f, 16, wmma::mem_row_major);
    __syncwarp();
    const float* sp = stage + lane * 8;
    __nv_bfloat162 h[4];
#pragma unroll
    for (int e = 0; e < 4; e++) {
        h[e].x = __float2bfloat16(sp[e * 2]     * scale);
        h[e].y = __float2bfloat16(sp[e * 2 + 1] * scale);
    }
    bf16* gp = gptr + (long long)(lane >> 1) * ldc + (lane & 1) * 8;
    *(uint4*)gp = *(uint4*)h;
    __syncwarp();
}

// =====================================================================
// bf16 WMMA GEMM (NN): optional fp32 out C, optional bf16 out Cbf,
// optional fp32 residual Res, optional relu. 128x128x32 tile, 8 warps.
// =====================================================================
__global__ void __launch_bounds__(256) bgemm_nn(
    const bf16* __restrict__ A, int lda, long long sA,
    const bf16* __restrict__ Bm, int ldb, long long sB,
    float* __restrict__ C, bf16* __restrict__ Cbf, int ldc, long long sC,
    const float* __restrict__ Res, int K, int relu)
{
    const int z = blockIdx.z;
    A  += (long long)z * sA;
    Bm += (long long)z * sB;
    if (C)   C   += (long long)z * sC;
    if (Cbf) Cbf += (long long)z * sC;
    if (Res) Res += (long long)z * sC;

    const int m0 = blockIdx.y * 128, n0 = blockIdx.x * 128;

    __shared__ __align__(16) bf16 As[128][40];
    __shared__ __align__(16) bf16 Bs[32][136];
    __shared__ __align__(16) float stage[8][264];

    const int tid  = threadIdx.x;
    const int warp = tid >> 5;
    const int lane = tid & 31;
    const int wm   = warp & 1;
    const int wn   = warp >> 1;

    wmma::fragment<wmma::accumulator, 16, 16, 16, float> acc[4][2];
    if (Res) {
#pragma unroll
        for (int i = 0; i < 4; i++)
#pragma unroll
            for (int j = 0; j < 2; j++)
                wmma::load_matrix_sync(acc[i][j],
                    Res + (long long)(m0 + wm * 64 + i * 16) * ldc + n0 + wn * 32 + j * 16,
                    ldc, wmma::mem_row_major);
    } else {
#pragma unroll
        for (int i = 0; i < 4; i++)
#pragma unroll
            for (int j = 0; j < 2; j++)
                wmma::fill_fragment(acc[i][j], 0.f);
    }

    const int arow = tid >> 2,  acg = (tid & 3) * 8;
    const int brow = tid >> 4,  bcg = (tid & 15) * 8;

    for (int k0 = 0; k0 < K; k0 += 32) {
        uint4 a0 = *(const uint4*)(A + (long long)(m0 + arow)      * lda + k0 + acg);
        uint4 a1 = *(const uint4*)(A + (long long)(m0 + arow + 64) * lda + k0 + acg);
        uint4 b0 = *(const uint4*)(Bm + (long long)(k0 + brow)      * ldb + n0 + bcg);
        uint4 b1 = *(const uint4*)(Bm + (long long)(k0 + brow + 16) * ldb + n0 + bcg);
        __syncthreads();
        *(uint4*)&As[arow][acg]      = a0;
        *(uint4*)&As[arow + 64][acg] = a1;
        *(uint4*)&Bs[brow][bcg]      = b0;
        *(uint4*)&Bs[brow + 16][bcg] = b1;
        __syncthreads();
#pragma unroll
        for (int kk = 0; kk < 32; kk += 16) {
            wmma::fragment<wmma::matrix_a, 16, 16, 16, bf16, wmma::row_major> af[4];
            wmma::fragment<wmma::matrix_b, 16, 16, 16, bf16, wmma::row_major> bfr[2];
#pragma unroll
            for (int i = 0; i < 4; i++)
                wmma::load_matrix_sync(af[i], &As[wm * 64 + i * 16][kk], 40);
#pragma unroll
            for (int j = 0; j < 2; j++)
                wmma::load_matrix_sync(bfr[j], &Bs[kk][wn * 32 + j * 16], 136);
#pragma unroll
            for (int i = 0; i < 4; i++)
#pragma unroll
                for (int j = 0; j < 2; j++)
                    wmma::mma_sync(acc[i][j], af[i], bfr[j], acc[i][j]);
        }
    }

#pragma unroll
    for (int i = 0; i < 4; i++)
#pragma unroll
        for (int j = 0; j < 2; j++) {
            if (relu) {
#pragma unroll
                for (int e = 0; e < acc[i][j].num_elements; e++)
                    acc[i][j].x[e] = fmaxf(acc[i][j].x[e], 0.f);
            }
            const long long off = (long long)(m0 + wm * 64 + i * 16) * ldc + n0 + wn * 32 + j * 16;
            if (C)
                wmma::store_matrix_sync(C + off, acc[i][j], ldc, wmma::mem_row_major);
            if (Cbf)
                frag_to_bf16(&stage[warp][0], acc[i][j], Cbf + off, ldc, lane, 1.f);
        }
}

// =====================================================================
// bf16 WMMA scores (layer 2, NT): bf16 out = 0.125 * Q @ K^T
// =====================================================================
__global__ void __launch_bounds__(256) bscores(
    const bf16* __restrict__ Q, const bf16* __restrict__ Kv, bf16* __restrict__ S)
{
    const int z = blockIdx.z;
    const int b = z >> 3, h = z & 7;
    const bf16* Ab = Q  + ((long long)b * TT) * DD + h * DHH;
    const bf16* Bb = Kv + ((long long)b * TT) * DD + h * DHH;
    bf16* Cb = S + (long long)z * TT * TT;

    const int m0 = blockIdx.y * 128, n0 = blockIdx.x * 128;

    __shared__ __align__(16) bf16 As[128][40];
    __shared__ __align__(16) bf16 Ks[128][40];
    __shared__ __align__(16) float stage[8][264];

    const int tid  = threadIdx.x;
    const int warp = tid >> 5;
    const int lane = tid & 31;
    const int wm   = warp & 1;
    const int wn   = warp >> 1;

    wmma::fragment<wmma::accumulator, 16, 16, 16, float> acc[4][2];
#pragma unroll
    for (int i = 0; i < 4; i++)
#pragma unroll
        for (int j = 0; j < 2; j++)
            wmma::fill_fragment(acc[i][j], 0.f);

    const int arow = tid >> 2, acg = (tid & 3) * 8;

#pragma unroll
    for (int k0 = 0; k0 < DHH; k0 += 32) {
        uint4 a0 = *(const uint4*)(Ab + (long long)(m0 + arow)      * DD + k0 + acg);
        uint4 a1 = *(const uint4*)(Ab + (long long)(m0 + arow + 64) * DD + k0 + acg);
        uint4 b0 = *(const uint4*)(Bb + (long long)(n0 + arow)      * DD + k0 + acg);
        uint4 b1 = *(const uint4*)(Bb + (long long)(n0 + arow + 64) * DD + k0 + acg);
        __syncthreads();
        *(uint4*)&As[arow][acg]      = a0;
        *(uint4*)&As[arow + 64][acg] = a1;
        *(uint4*)&Ks[arow][acg]      = b0;
        *(uint4*)&Ks[arow + 64][acg] = b1;
        __syncthreads();
#pragma unroll
        for (int kk = 0; kk < 32; kk += 16) {
            wmma::fragment<wmma::matrix_a, 16, 16, 16, bf16, wmma::row_major> af[4];
            wmma::fragment<wmma::matrix_b, 16, 16, 16, bf16, wmma::col_major> bfr[2];
#pragma unroll
            for (int i = 0; i < 4; i++)
                wmma::load_matrix_sync(af[i], &As[wm * 64 + i * 16][kk], 40);
#pragma unroll
            for (int j = 0; j < 2; j++)
                wmma::load_matrix_sync(bfr[j], &Ks[wn * 32 + j * 16][kk], 40);
#pragma unroll
            for (int i = 0; i < 4; i++)
#pragma unroll
                for (int j = 0; j < 2; j++)
                    wmma::mma_sync(acc[i][j], af[i], bfr[j], acc[i][j]);
        }
    }

#pragma unroll
    for (int i = 0; i < 4; i++)
#pragma unroll
        for (int j = 0; j < 2; j++) {
            const long long off = (long long)(m0 + wm * 64 + i * 16) * TT + n0 + wn * 32 + j * 16;
            frag_to_bf16(&stage[warp][0], acc[i][j], Cb + off, TT, lane, 0.125f);
        }
}

// =====================================================================
// bf16 WMMA PV -> bf16 ctx. 128x64x32 tile, 8 warps (4M x 2N).
// =====================================================================
__global__ void __launch_bounds__(256) bpv(
    const bf16* __restrict__ P, const bf16* __restrict__ V, bf16* __restrict__ ctx)
{
    const int z = blockIdx.y;
    const int b = z >> 3, h = z & 7;
    const bf16* Ab = P + (long long)z * TT * TT;
    const bf16* Bb = V + ((long long)b * TT) * DD + h * DHH;
    bf16* Cb = ctx + ((long long)b * TT) * DD + h * DHH;

    const int m0 = blockIdx.x * 128;

    __shared__ __align__(16) bf16 As[128][40];
    __shared__ __align__(16) bf16 Bs[32][72];
    __shared__ __align__(16) float stage[8][264];

    const int tid  = threadIdx.x;
    const int warp = tid >> 5;
    const int lane = tid & 31;
    const int wm   = warp & 3;
    const int wn   = warp >> 2;

    wmma::fragment<wmma::accumulator, 16, 16, 16, float> acc[2][2];
#pragma unroll
    for (int i = 0; i < 2; i++)
#pragma unroll
        for (int j = 0; j < 2; j++)
            wmma::fill_fragment(acc[i][j], 0.f);

    const int arow = tid >> 2, acg = (tid & 3) * 8;
    const int brow = tid >> 3, bcg = (tid & 7) * 8;

    for (int k0 = 0; k0 < TT; k0 += 32) {
        uint4 a0 = *(const uint4*)(Ab + (long long)(m0 + arow)      * TT + k0 + acg);
        uint4 a1 = *(const uint4*)(Ab + (long long)(m0 + arow + 64) * TT + k0 + acg);
        uint4 b0 = *(const uint4*)(Bb + (long long)(k0 + brow) * DD + bcg);
        __syncthreads();
        *(uint4*)&As[arow][acg]      = a0;
        *(uint4*)&As[arow + 64][acg] = a1;
        *(uint4*)&Bs[brow][bcg]      = b0;
        __syncthreads();
#pragma unroll
        for (int kk = 0; kk < 32; kk += 16) {
            wmma::fragment<wmma::matrix_a, 16, 16, 16, bf16, wmma::row_major> af[2];
            wmma::fragment<wmma::matrix_b, 16, 16, 16, bf16, wmma::row_major> bfr[2];
#pragma unroll
            for (int i = 0; i < 2; i++)
                wmma::load_matrix_sync(af[i], &As[wm * 32 + i * 16][kk], 40);
#pragma unroll
            for (int j = 0; j < 2; j++)
                wmma::load_matrix_sync(bfr[j], &Bs[kk][wn * 32 + j * 16], 72);
#pragma unroll
            for (int i = 0; i < 2; i++)
#pragma unroll
                for (int j = 0; j < 2; j++)
                    wmma::mma_sync(acc[i][j], af[i], bfr[j], acc[i][j]);
        }
    }

#pragma unroll
    for (int i = 0; i < 2; i++)
#pragma unroll
        for (int j = 0; j < 2; j++) {
            const long long off = (long long)(m0 + wm * 32 + i * 16) * DD + wn * 32 + j * 16;
            frag_to_bf16(&stage[warp][0], acc[i][j], Cb + off, DD, lane, 1.f);
        }
}

// =====================================================================
// Layer-1 row softmax (fp32 in/out + bf16 probs out), no mask.
// =====================================================================
__global__ void __launch_bounds__(256) softmax_rows_k(float* __restrict__ S,
                                                      bf16* __restrict__ Pbf)
{
    const long long r = blockIdx.x;
    float* row = S + r * TT;
    bf16*  rbf = Pbf + r * TT;
    const int tid = threadIdx.x;

    __shared__ float sh[256];

    float v[4];
    float mx = -3.4e38f;
#pragma unroll
    for (int i = 0; i < 4; i++) {
        v[i] = row[tid + i * 256];
        mx = fmaxf(mx, v[i]);
    }
    sh[tid] = mx; __syncthreads();
    for (int s = 128; s > 0; s >>= 1) { if (tid < s) sh[tid] = fmaxf(sh[tid], sh[tid + s]); __syncthreads(); }
    mx = sh[0]; __syncthreads();

    float e[4];
    float sum = 0.f;
#pragma unroll
    for (int i = 0; i < 4; i++) { e[i] = expf(v[i] - mx); sum += e[i]; }
    sh[tid] = sum; __syncthreads();
    for (int s = 128; s > 0; s >>= 1) { if (tid < s) sh[tid] += sh[tid + s]; __syncthreads(); }
    const float inv = 1.f / sh[0];

#pragma unroll
    for (int i = 0; i < 4; i++) {
        float p = e[i] * inv;
        row[tid + i * 256] = p;
        rbf[tid + i * 256] = __float2bfloat16(p);
    }
}

// =====================================================================
// Layer-2 masked softmax, bf16 in-place (continuous path).
// =====================================================================
__global__ void __launch_bounds__(256) softmax2_bf(bf16* __restrict__ P,
                                                   const int* __restrict__ ids)
{
    const long long r = blockIdx.x;
    const int q  = (int)(r & (TT - 1));
    const int bh = (int)(r >> 10);
    const int b  = bh >> 3;
    bf16* row = P + r * TT;
    const int tid = threadIdx.x;

    __shared__ float sh[256];

    const float NEG = __int_as_float(0xff800000);
    const int idbase = b * TT;
    const int qid = ids[idbase + q];

    float v[4];
    float mx = -3.4e38f;
#pragma unroll
    for (int i = 0; i < 4; i++) {
        int k = tid + i * 256;
        float x = __bfloat162float(row[k]);
        if (ids[idbase + k] != qid) x = NEG;
        v[i] = x;
        mx = fmaxf(mx, x);
    }
    sh[tid] = mx; __syncthreads();
    for (int s = 128; s > 0; s >>= 1) { if (tid < s) sh[tid] = fmaxf(sh[tid], sh[tid + s]); __syncthreads(); }
    mx = sh[0]; __syncthreads();

    float e[4];
    float sum = 0.f;
#pragma unroll
    for (int i = 0; i < 4; i++) { e[i] = expf(v[i] - mx); sum += e[i]; }
    sh[tid] = sum; __syncthreads();
    for (int s = 128; s > 0; s >>= 1) { if (tid < s) sh[tid] += sh[tid + s]; __syncthreads(); }
    const float inv = 1.f / sh[0];

#pragma unroll
    for (int i = 0; i < 4; i++)
        row[tid + i * 256] = __float2bfloat16(e[i] * inv);
}

// fp32 column sum (double accum) — layer 1 (threshold-critical)
__global__ void __launch_bounds__(256) colsum_k(const float* __restrict__ P,
                                                float* __restrict__ w)
{
    const int b = blockIdx.x;
    const int k = blockIdx.y * 256 + threadIdx.x;
    const float* p = P + (long long)b * HH * TT * TT + k;
    double s0 = 0, s1 = 0, s2 = 0, s3 = 0;
    for (long long i = 0; i < (long long)HH * TT; i += 4) {
        s0 += (double)p[i * TT];
        s1 += (double)p[(i + 1) * TT];
        s2 += (double)p[(i + 2) * TT];
        s3 += (double)p[(i + 3) * TT];
    }
    w[b * TT + k] = (float)(((s0 + s1) + (s2 + s3)) * (1.0 / HH));
}

// bf16 column sum — layer 2 (continuous path)
__global__ void __launch_bounds__(256) colsum_bf(const bf16* __restrict__ P,
                                                 float* __restrict__ w)
{
    const int b = blockIdx.x;
    const int k = blockIdx.y * 256 + threadIdx.x;
    const bf16* p = P + (long long)b * HH * TT * TT + k;
    double s0 = 0, s1 = 0, s2 = 0, s3 = 0;
    for (long long i = 0; i < (long long)HH * TT; i += 4) {
        s0 += (double)__bfloat162float(p[i * TT]);
        s1 += (double)__bfloat162float(p[(i + 1) * TT]);
        s2 += (double)__bfloat162float(p[(i + 2) * TT]);
        s3 += (double)__bfloat162float(p[(i + 3) * TT]);
    }
    w[b * TT + k] = (float)(((s0 + s1) + (s2 + s3)) * (1.0 / HH));
}

__global__ void __launch_bounds__(256) minmax_k(const float* __restrict__ w,
                                                float* __restrict__ mm)
{
    const int b = blockIdx.x, tid = threadIdx.x;
    __shared__ float smn[256], smx[256];
    float mn = 3.4e38f, mx = -3.4e38f;
    for (int t = tid; t < TT; t += 256) {
        float x = w[b * TT + t];
        mn = fminf(mn, x); mx = fmaxf(mx, x);
    }
    smn[tid] = mn; smx[tid] = mx; __syncthreads();
    for (int s = 128; s > 0; s >>= 1) {
        if (tid < s) { smn[tid] = fminf(smn[tid], smn[tid + s]); smx[tid] = fmaxf(smx[tid], smx[tid + s]); }
        __syncthreads();
    }
    if (tid == 0) { mm[b * 2] = smn[0]; mm[b * 2 + 1] = smx[0]; }
}

__global__ void winscan_k(const float* __restrict__ w, const float* __restrict__ mm,
                          int* __restrict__ ids)
{
    const int b = threadIdx.x;
    if (b >= BB) return;
    const float mn  = mm[b * 2];
    const float den = mm[b * 2 + 1] - mn + 1e-8f;
    const float* wb = w + b * TT;
    int* idb = ids + b * TT;

    bool cur = ((wb[0] - mn) / den) >= 0.5f;
    int start = 0, wid = 0;
    idb[0] = 0;
    for (int t = 1; t < TT; t++) {
        bool wt = ((wb[t] - mn) / den) >= 0.5f;
        if (wt != cur) {
            cur = wt;
            if (start + 1 != t) { start = t; wid++; }
        }
        idb[t] = wid;
    }
}

__global__ void __launch_bounds__(256) softmax1d_k(const float* __restrict__ w,
                                                   float* __restrict__ wl)
{
    const int b = blockIdx.x, tid = threadIdx.x;
    __shared__ float sh[256];
    float v[4];
    float mx = -3.4e38f;
#pragma unroll
    for (int i = 0; i < 4; i++) { v[i] = w[b * TT + tid + i * 256]; mx = fmaxf(mx, v[i]); }
    sh[tid] = mx; __syncthreads();
    for (int s = 128; s > 0; s >>= 1) { if (tid < s) sh[tid] = fmaxf(sh[tid], sh[tid + s]); __syncthreads(); }
    mx = sh[0]; __syncthreads();
    float e[4], sum = 0.f;
#pragma unroll
    for (int i = 0; i < 4; i++) { e[i] = expf(v[i] - mx); sum += e[i]; }
    sh[tid] = sum; __syncthreads();
    for (int s = 128; s > 0; s >>= 1) { if (tid < s) sh[tid] += sh[tid + s]; __syncthreads(); }
    const float inv = 1.f / sh[0];
#pragma unroll
    for (int i = 0; i < 4; i++) wl[b * TT + tid + i * 256] = e[i] * inv;
}

// in-place LayerNorm over D=512 + optional bf16 dual write
__global__ void __launch_bounds__(256) ln_k(float* __restrict__ X, bf16* __restrict__ Xbf)
{
    const long long r = blockIdx.x;
    float* row = X + r * DD;
    const int tid = threadIdx.x;
    __shared__ float sh[256];

    float x0 = row[tid], x1 = row[tid + 256];
    sh[tid] = x0 + x1; __syncthreads();
    for (int s = 128; s > 0; s >>= 1) { if (tid < s) sh[tid] += sh[tid + s]; __syncthreads(); }
    const float mean = sh[0] * (1.f / DD);
    __syncthreads();

    const float d0 = x0 - mean, d1 = x1 - mean;
    sh[tid] = d0 * d0 + d1 * d1; __syncthreads();
    for (int s = 128; s > 0; s >>= 1) { if (tid < s) sh[tid] += sh[tid + s]; __syncthreads(); }
    const float var = sh[0] * (1.f / DD);
    const float rs = 1.f / sqrtf(var + 1e-5f);
    const float y0 = d0 * rs, y1 = d1 * rs;
    row[tid] = y0;
    row[tid + 256] = y1;
    if (Xbf) {
        Xbf[r * DD + tid]       = __float2bfloat16(y0);
        Xbf[r * DD + tid + 256] = __float2bfloat16(y1);
    }
}

// float -> bf16 conversion
__global__ void __launch_bounds__(256) f2bf_k(const float* __restrict__ src,
                                              bf16* __restrict__ dst, long long n)
{
    const long long i = ((long long)blockIdx.x * 256 + threadIdx.x) * 4;
    if (i >= n) return;
    float4 v = *(const float4*)(src + i);
    __nv_bfloat162 p0, p1;
    p0.x = __float2bfloat16(v.x); p0.y = __float2bfloat16(v.y);
    p1.x = __float2bfloat16(v.z); p1.y = __float2bfloat16(v.w);
    *(__nv_bfloat162*)(dst + i)     = p0;
    *(__nv_bfloat162*)(dst + i + 2) = p1;
}

// out[:, 0:T, :] = 0 ; out[:, T:2T, :] = x
__global__ void __launch_bounds__(256) outinit_k(const float* __restrict__ x,
                                                 float* __restrict__ out)
{
    const long long idx = (long long)blockIdx.x * 256 + threadIdx.x;
    const int d = (int)(idx & (DD - 1));
    const long long rb = idx >> 9;
    const int r = (int)(rb & (2 * TT - 1));
    const int b = (int)(rb >> 11);
    out[idx] = (r < TT) ? 0.f : x[((long long)b * TT + (r - TT)) * DD + d];
}

// segmented pooling
__global__ void __launch_bounds__(512) pool_k(const float* __restrict__ outl,
                                              const float* __restrict__ wl,
                                              const int* __restrict__ ids,
                                              float* __restrict__ out)
{
    const int b = blockIdx.x, d = threadIdx.x;
    __shared__ int   sids[TT];
    __shared__ float swl[TT];
    for (int t = d; t < TT; t += 512) {
        sids[t] = ids[b * TT + t];
        swl[t]  = wl[b * TT + t];
    }
    __syncthreads();

    const float* xb = outl + (long long)b * TT * DD + d;
    float acc = 0.f;
    for (int t0 = 0; t0 < TT; t0 += 16) {
        float vals[16];
#pragma unroll
        for (int u = 0; u < 16; u++) vals[u] = xb[(long long)(t0 + u) * DD];
#pragma unroll
        for (int u = 0; u < 16; u++) {
            const int t = t0 + u;
            acc = fmaf(vals[u], swl[t], acc);
            const int curid = sids[t];
            const bool flush = (t == TT - 1) || (sids[t + 1] != curid);
            if (flush) {
                out[((long long)b * 2 * TT + curid) * DD + d] = acc;
                acc = 0.f;
            }
        }
    }
}

__global__ void __launch_bounds__(256) mapping_k(const int* __restrict__ ids,
                                                 float* __restrict__ out2)
{
    const long long idx = (long long)blockIdx.x * 256 + threadIdx.x;
    const int j = (int)(idx & (TT - 1));
    const long long wb = idx >> 10;
    const int wrow = (int)(wb & (TT - 1));
    const int b = (int)(wb >> 10);
    out2[idx] = (ids[b * TT + j] == wrow) ? 1.f : 0.f;
}

// =====================================================================
// host
// =====================================================================
extern "C" void kernel_launch(void* const* d_in, const int* in_sizes, int n_in,
                              void* d_out, int out_size)
{
    (void)in_sizes; (void)n_in; (void)out_size;
    const float* x       = (const float*)d_in[0];
    const float* v_qkv_w = (const float*)d_in[1];
    const float* v_out_w = (const float*)d_in[2];
    const float* v_w1    = (const float*)d_in[3];
    const float* v_w2    = (const float*)d_in[4];
    const float* l_qkv_w = (const float*)d_in[5];
    const float* l_out_w = (const float*)d_in[6];
    const float* l_w1    = (const float*)d_in[7];
    const float* l_w2    = (const float*)d_in[8];
    float* out = (float*)d_out;

    float *qkv, *scores, *tmp, *outv, *outl, *w, *mm, *wl;
    int* ids;
    bf16 *wbf, *xbf, *qkvbf, *probsbf, *ctxbf, *tmpbf, *outvbf, *ffbf;
    cudaGetSymbolAddress((void**)&qkv,    g_qkv);
    cudaGetSymbolAddress((void**)&scores, g_scores);
    cudaGetSymbolAddress((void**)&tmp,    g_tmp);
    cudaGetSymbolAddress((void**)&outv,   g_outv);
    cudaGetSymbolAddress((void**)&outl,   g_outl);
    cudaGetSymbolAddress((void**)&w,      g_w);
    cudaGetSymbolAddress((void**)&mm,     g_mm);
    cudaGetSymbolAddress((void**)&ids,    g_ids);
    cudaGetSymbolAddress((void**)&wl,     g_wl);
    cudaGetSymbolAddress((void**)&wbf,    g_wbf);
    cudaGetSymbolAddress((void**)&xbf,    g_xbf);
    cudaGetSymbolAddress((void**)&qkvbf,  g_qkvbf);
    cudaGetSymbolAddress((void**)&probsbf,g_probsbf);
    cudaGetSymbolAddress((void**)&ctxbf,  g_ctxbf);
    cudaGetSymbolAddress((void**)&tmpbf,  g_tmpbf);
    cudaGetSymbolAddress((void**)&outvbf, g_outvbf);
    cudaGetSymbolAddress((void**)&ffbf,   g_ffbf);

    const dim3 blk(256);
    const long long sQKVw = (long long)DD * DD;
    const long long sQKVc = (long long)BT * DD;

    // ---- weight + input conversions (small) ----
    auto cvt = [&](const float* s, bf16* d, long long n) {
        f2bf_k<<<(unsigned)((n + 1023) / 1024), blk>>>(s, d, n);
    };
    cvt(v_qkv_w, wbf + OFF_VQKV, 3LL * DD * DD);
    cvt(v_out_w, wbf + OFF_VOUT, (long long)DD * DD);
    cvt(v_w1,    wbf + OFF_VW1,  (long long)DD * FFD);
    cvt(v_w2,    wbf + OFF_VW2,  (long long)FFD * DD);
    cvt(l_qkv_w, wbf + OFF_LQKV, 3LL * DD * DD);
    cvt(l_out_w, wbf + OFF_LOUT, (long long)DD * DD);
    cvt(l_w1,    wbf + OFF_LW1,  (long long)DD * FFD);
    cvt(l_w2,    wbf + OFF_LW2,  (long long)FFD * DD);
    cvt(x, xbf, sQKVc);

    // ---------------- layer 1 (vanilla) ----------------
    // Q,K in fp32 (threshold-critical)
    sgemm128<<<dim3(DD / 128, BT / 128, 2), blk>>>(x, DD, 0, v_qkv_w, DD, sQKVw,
                                                   qkv, DD, sQKVc, DD);
    // V in bf16 (bf16-only output)
    bgemm_nn<<<dim3(DD / 128, BT / 128, 1), blk>>>(xbf, DD, 0,
                                                   wbf + OFF_VQKV + 2 * sQKVw, DD, 0,
                                                   nullptr, qkvbf + 2 * sQKVc, DD, 0,
                                                   nullptr, DD, 0);
    attn_scores128<<<dim3(TT / 128, TT / 128, BHH), blk>>>(qkv, qkv + sQKVc, scores);
    softmax_rows_k<<<BHH * TT, blk>>>(scores, probsbf);
    colsum_k<<<dim3(BB, TT / 256), blk>>>(scores, w);
    minmax_k<<<BB, blk>>>(w, mm);
    winscan_k<<<1, 32>>>(w, mm, ids);
    bpv<<<dim3(TT / 128, BHH), blk>>>(probsbf, qkvbf + 2 * sQKVc, ctxbf);
    bgemm_nn<<<dim3(DD / 128, BT / 128, 1), blk>>>(ctxbf, DD, 0, wbf + OFF_VOUT, DD, 0,
                                                   tmp, nullptr, DD, 0, x, DD, 0);
    ln_k<<<BT, blk>>>(tmp, tmpbf);
    bgemm_nn<<<dim3(FFD / 128, BT / 128, 1), blk>>>(tmpbf, DD, 0, wbf + OFF_VW1, FFD, 0,
                                                    nullptr, ffbf, FFD, 0, nullptr, DD, 1);
    bgemm_nn<<<dim3(DD / 128, BT / 128, 1), blk>>>(ffbf, FFD, 0, wbf + OFF_VW2, DD, 0,
                                                   outv, nullptr, DD, 0, tmp, FFD, 0);
    ln_k<<<BT, blk>>>(outv, outvbf);

    // ---------------- layer 2 (windowed, bf16 throughout) ----------------
    bgemm_nn<<<dim3(DD / 128, BT / 128, 3), blk>>>(outvbf, DD, 0, wbf + OFF_LQKV, DD, sQKVw,
                                                   nullptr, qkvbf, DD, sQKVc,
                                                   nullptr, DD, 0);
    bscores<<<dim3(TT / 128, TT / 128, BHH), blk>>>(qkvbf, qkvbf + sQKVc, probsbf);
    softmax2_bf<<<BHH * TT, blk>>>(probsbf, ids);
    colsum_bf<<<dim3(BB, TT / 256), blk>>>(probsbf, w);
    softmax1d_k<<<BB, blk>>>(w, wl);
    bpv<<<dim3(TT / 128, BHH), blk>>>(probsbf, qkvbf + 2 * sQKVc, ctxbf);
    bgemm_nn<<<dim3(DD / 128, BT / 128, 1), blk>>>(ctxbf, DD, 0, wbf + OFF_LOUT, DD, 0,
                                                   tmp, nullptr, DD, 0, outv, DD, 0);
    ln_k<<<BT, blk>>>(tmp, tmpbf);
    bgemm_nn<<<dim3(FFD / 128, BT / 128, 1), blk>>>(tmpbf, DD, 0, wbf + OFF_LW1, FFD, 0,
                                                    nullptr, ffbf, FFD, 0, nullptr, DD, 1);
    bgemm_nn<<<dim3(DD / 128, BT / 128, 1), blk>>>(ffbf, FFD, 0, wbf + OFF_LW2, DD, 0,
                                                   outl, nullptr, DD, 0, tmp, FFD, 0);
    ln_k<<<BT, blk>>>(outl, nullptr);

    // ---------------- outputs ----------------
    const long long n1 = (long long)BB * 2 * TT * DD;
    outinit_k<<<(unsigned)(n1 / 256), blk>>>(x, out);
    pool_k<<<BB, 512>>>(outl, wl, ids, out);
    mapping_k<<<(unsigned)(((long long)BB * TT * TT) / 256), blk>>>(ids, out + n1);
}

// round 17
// speedup vs baseline: 2.1936x; 2.1912x over previous
#include <cuda_runtime.h>
#include <cuda_bf16.h>
#include <mma.h>
#include <math.h>

using namespace nvcuda;
typedef __nv_bfloat16 bf16;

// ---------------- problem constants ----------------
#define BB   8
#define HH   8
#define TT   1024
#define DD   512
#define DHH  64
#define FFD  2048
#define BT   8192        // B*T
#define BHH  64          // B*H

// weight offsets in the packed bf16 weight buffer
#define OFF_VQKV 0LL
#define OFF_VOUT (3LL*DD*DD)
#define OFF_VW1  (OFF_VOUT + (long long)DD*DD)
#define OFF_VW2  (OFF_VW1 + (long long)DD*FFD)
#define OFF_LQKV (OFF_VW2 + (long long)FFD*DD)
#define OFF_LOUT (OFF_LQKV + 3LL*DD*DD)
#define OFF_LW1  (OFF_LOUT + (long long)DD*DD)
#define OFF_LW2  (OFF_LW1 + (long long)DD*FFD)
#define WBF_TOTAL (OFF_LW2 + (long long)FFD*DD)

// ---------------- device scratch ----------------
__device__ float g_qkv[2ll * BT * DD];                 // fp32 Q,K (layer 1 only)
__device__ float g_scores[(long long)BHH * TT * TT];   // fp32 scores (layer 1)
__device__ float g_tmp[(long long)BT * DD];
__device__ float g_outv[(long long)BT * DD];
__device__ float g_outl[(long long)BT * DD];
__device__ float  g_w[BB * TT];
__device__ double g_wd1[BB * TT];
__device__ double g_wd2[BB * TT];
__device__ float g_mm[BB * 2];
__device__ int   g_ids[BB * TT];
__device__ float g_wl[BB * TT];

__device__ bf16 g_wbf[WBF_TOTAL];
__device__ bf16 g_xbf[(long long)BT * DD];
__device__ bf16 g_qkvbf[3ll * BT * DD];
__device__ bf16 g_probsbf[(long long)BHH * TT * TT];   // bf16 scores->probs (both layers)
__device__ bf16 g_ctxbf[(long long)BT * DD];
__device__ bf16 g_tmpbf[(long long)BT * DD];
__device__ bf16 g_outvbf[(long long)BT * DD];
__device__ bf16 g_ffbf[(long long)BT * FFD];

// ---------------- packed f32x2 helpers ----------------
#define PACK2(d, f)  asm("mov.b64 %0, {%1, %1};" : "=l"(d) : "f"(f))
#define FMA2(acc, a2, b2) \
    asm("fma.rn.f32x2 %0, %1, %2, %3;" : "=l"(acc) : "l"(a2), "l"(b2), "l"(acc))
#define MUL2(d, a2, b2) \
    asm("mul.rn.f32x2 %0, %1, %2;" : "=l"(d) : "l"(a2), "l"(b2))

// one 8x8 microtile step: a from As row, b from Bs row, packed accumulators
__device__ __forceinline__ void fma_tile8x8(
    const float* __restrict__ arow, const float* __restrict__ brow,
    unsigned long long acc2[8][4])
{
    float4 a0 = *(const float4*)(arow);
    float4 a1 = *(const float4*)(arow + 4);
    ulonglong2 q0 = *(const ulonglong2*)(brow);
    ulonglong2 q1 = *(const ulonglong2*)(brow + 4);
    unsigned long long bb[4] = {q0.x, q0.y, q1.x, q1.y};
    float a[8] = {a0.x, a0.y, a0.z, a0.w, a1.x, a1.y, a1.z, a1.w};
#pragma unroll
    for (int i = 0; i < 8; i++) {
        unsigned long long ad;
        PACK2(ad, a[i]);
#pragma unroll
        for (int j = 0; j < 4; j++)
            FMA2(acc2[i][j], ad, bb[j]);
    }
}

// =====================================================================
// fp32 SGEMM NN 128x128x8 with packed f32x2 FMA (layer-1 Q,K proj only;
// bit-identical fp32 numerics, threshold-critical path).
// =====================================================================
__global__ void __launch_bounds__(256) sgemm128(
    const float* __restrict__ A, int lda, long long sA,
    const float* __restrict__ Bm, int ldb, long long sB,
    float* __restrict__ C, int ldc, long long sC, int K)
{
    const int z = blockIdx.z;
    A  += (long long)z * sA;
    Bm += (long long)z * sB;
    C  += (long long)z * sC;

    const int m0 = blockIdx.y * 128, n0 = blockIdx.x * 128;

    __shared__ __align__(16) float As[8][128];
    __shared__ __align__(16) float Bs[8][132];

    const int tid = threadIdx.x;
    const int ty  = tid >> 4;
    const int tx  = tid & 15;

    const int arow = tid >> 1;
    const int acol = (tid & 1) << 2;
    const int brow = tid >> 5;
    const int bcol = (tid & 31) << 2;

    const float* Ag = A + (long long)(m0 + arow) * lda + acol;
    const float* Bg = Bm + (long long)brow * ldb + n0 + bcol;

    float4 pa = *(const float4*)Ag;
    float4 pb = *(const float4*)Bg;

    unsigned long long acc2[8][4];
#pragma unroll
    for (int i = 0; i < 8; i++)
#pragma unroll
        for (int j = 0; j < 4; j++) acc2[i][j] = 0ULL;

    for (int k0 = 0; k0 < K; k0 += 8) {
        As[acol + 0][arow] = pa.x;
        As[acol + 1][arow] = pa.y;
        As[acol + 2][arow] = pa.z;
        As[acol + 3][arow] = pa.w;
        *(float4*)&Bs[brow][bcol] = pb;
        __syncthreads();
        if (k0 + 8 < K) {
            pa = *(const float4*)(Ag + k0 + 8);
            pb = *(const float4*)(Bg + (long long)(k0 + 8) * ldb);
        }
#pragma unroll
        for (int kk = 0; kk < 8; kk++)
            fma_tile8x8(&As[kk][ty * 8], &Bs[kk][tx * 8], acc2);
        __syncthreads();
    }

#pragma unroll
    for (int i = 0; i < 8; i++) {
        float* cp = C + (long long)(m0 + ty * 8 + i) * ldc + n0 + tx * 8;
        ulonglong2 o0; o0.x = acc2[i][0]; o0.y = acc2[i][1];
        ulonglong2 o1; o1.x = acc2[i][2]; o1.y = acc2[i][3];
        *(ulonglong2*)cp       = o0;
        *(ulonglong2*)(cp + 4) = o1;
    }
}

// =====================================================================
// fp32 NT attention scores (layer 1): S = 0.125 * Q @ K^T, f32x2 FMA.
// =====================================================================
__global__ void __launch_bounds__(256) attn_scores128(
    const float* __restrict__ Q, const float* __restrict__ Km, float* __restrict__ S)
{
    const int z = blockIdx.z;
    const int b = z >> 3, h = z & 7;
    const float* Ab = Q  + ((long long)b * TT) * DD + h * DHH;
    const float* Bb = Km + ((long long)b * TT) * DD + h * DHH;
    float* Cb = S + (long long)z * TT * TT;

    const int m0 = blockIdx.y * 128, n0 = blockIdx.x * 128;

    __shared__ __align__(16) float As[32][132];
    __shared__ __align__(16) float Bs[32][132];

    const int tid = threadIdx.x;
    const int ty  = tid >> 4;
    const int tx  = tid & 15;

    unsigned long long acc2[8][4];
#pragma unroll
    for (int i = 0; i < 8; i++)
#pragma unroll
        for (int j = 0; j < 4; j++) acc2[i][j] = 0ULL;

#pragma unroll
    for (int kc = 0; kc < DHH; kc += 32) {
        __syncthreads();
#pragma unroll
        for (int p = 0; p < 4; p++) {
            const int idx = p * 256 + tid;
            const int row = idx >> 3;
            const int c4  = (idx & 7) << 2;
            float4 va = *(const float4*)(Ab + (long long)(m0 + row) * DD + kc + c4);
            float4 vb = *(const float4*)(Bb + (long long)(n0 + row) * DD + kc + c4);
            As[c4 + 0][row] = va.x; As[c4 + 1][row] = va.y;
            As[c4 + 2][row] = va.z; As[c4 + 3][row] = va.w;
            Bs[c4 + 0][row] = vb.x; Bs[c4 + 1][row] = vb.y;
            Bs[c4 + 2][row] = vb.z; Bs[c4 + 3][row] = vb.w;
        }
        __syncthreads();
#pragma unroll
        for (int kk = 0; kk < 32; kk++)
            fma_tile8x8(&As[kk][ty * 8], &Bs[kk][tx * 8], acc2);
    }

    unsigned long long sc2;
    PACK2(sc2, 0.125f);
#pragma unroll
    for (int i = 0; i < 8; i++) {
        float* cp = Cb + (long long)(m0 + ty * 8 + i) * TT + n0 + tx * 8;
        ulonglong2 o0, o1;
        MUL2(o0.x, acc2[i][0], sc2);
        MUL2(o0.y, acc2[i][1], sc2);
        MUL2(o1.x, acc2[i][2], sc2);
        MUL2(o1.y, acc2[i][3], sc2);
        *(ulonglong2*)cp       = o0;
        *(ulonglong2*)(cp + 4) = o1;
    }
}

// helper: warp writes one 16x16 float fragment as bf16 via smem staging
__device__ __forceinline__ void frag_to_bf16(
    float* stage, const wmma::fragment<wmma::accumulator,16,16,16,float>& f,
    bf16* gptr, int ldc, int lane, float scale)
{
    wmma::store_matrix_sync(stage, f, 16, wmma::mem_row_major);
    __syncwarp();
    const float* sp = stage + lane * 8;
    __nv_bfloat162 h[4];
#pragma unroll
    for (int e = 0; e < 4; e++) {
        h[e].x = __float2bfloat16(sp[e * 2]     * scale);
        h[e].y = __float2bfloat16(sp[e * 2 + 1] * scale);
    }
    bf16* gp = gptr + (long long)(lane >> 1) * ldc + (lane & 1) * 8;
    *(uint4*)gp = *(uint4*)h;
    __syncwarp();
}

// =====================================================================
// bf16 WMMA GEMM (NN): optional fp32 out C, optional bf16 out Cbf,
// optional fp32 residual Res, optional relu. 128x128x32 tile, 8 warps.
// =====================================================================
__global__ void __launch_bounds__(256) bgemm_nn(
    const bf16* __restrict__ A, int lda, long long sA,
    const bf16* __restrict__ Bm, int ldb, long long sB,
    float* __restrict__ C, bf16* __restrict__ Cbf, int ldc, long long sC,
    const float* __restrict__ Res, int K, int relu)
{
    const int z = blockIdx.z;
    A  += (long long)z * sA;
    Bm += (long long)z * sB;
    if (C)   C   += (long long)z * sC;
    if (Cbf) Cbf += (long long)z * sC;
    if (Res) Res += (long long)z * sC;

    const int m0 = blockIdx.y * 128, n0 = blockIdx.x * 128;

    __shared__ __align__(16) bf16 As[128][40];
    __shared__ __align__(16) bf16 Bs[32][136];
    __shared__ __align__(16) float stage[8][264];

    const int tid  = threadIdx.x;
    const int warp = tid >> 5;
    const int lane = tid & 31;
    const int wm   = warp & 1;
    const int wn   = warp >> 1;

    wmma::fragment<wmma::accumulator, 16, 16, 16, float> acc[4][2];
    if (Res) {
#pragma unroll
        for (int i = 0; i < 4; i++)
#pragma unroll
            for (int j = 0; j < 2; j++)
                wmma::load_matrix_sync(acc[i][j],
                    Res + (long long)(m0 + wm * 64 + i * 16) * ldc + n0 + wn * 32 + j * 16,
                    ldc, wmma::mem_row_major);
    } else {
#pragma unroll
        for (int i = 0; i < 4; i++)
#pragma unroll
            for (int j = 0; j < 2; j++)
                wmma::fill_fragment(acc[i][j], 0.f);
    }

    const int arow = tid >> 2,  acg = (tid & 3) * 8;
    const int brow = tid >> 4,  bcg = (tid & 15) * 8;

    for (int k0 = 0; k0 < K; k0 += 32) {
        uint4 a0 = *(const uint4*)(A + (long long)(m0 + arow)      * lda + k0 + acg);
        uint4 a1 = *(const uint4*)(A + (long long)(m0 + arow + 64) * lda + k0 + acg);
        uint4 b0 = *(const uint4*)(Bm + (long long)(k0 + brow)      * ldb + n0 + bcg);
        uint4 b1 = *(const uint4*)(Bm + (long long)(k0 + brow + 16) * ldb + n0 + bcg);
        __syncthreads();
        *(uint4*)&As[arow][acg]      = a0;
        *(uint4*)&As[arow + 64][acg] = a1;
        *(uint4*)&Bs[brow][bcg]      = b0;
        *(uint4*)&Bs[brow + 16][bcg] = b1;
        __syncthreads();
#pragma unroll
        for (int kk = 0; kk < 32; kk += 16) {
            wmma::fragment<wmma::matrix_a, 16, 16, 16, bf16, wmma::row_major> af[4];
            wmma::fragment<wmma::matrix_b, 16, 16, 16, bf16, wmma::row_major> bfr[2];
#pragma unroll
            for (int i = 0; i < 4; i++)
                wmma::load_matrix_sync(af[i], &As[wm * 64 + i * 16][kk], 40);
#pragma unroll
            for (int j = 0; j < 2; j++)
                wmma::load_matrix_sync(bfr[j], &Bs[kk][wn * 32 + j * 16], 136);
#pragma unroll
            for (int i = 0; i < 4; i++)
#pragma unroll
                for (int j = 0; j < 2; j++)
                    wmma::mma_sync(acc[i][j], af[i], bfr[j], acc[i][j]);
        }
    }

#pragma unroll
    for (int i = 0; i < 4; i++)
#pragma unroll
        for (int j = 0; j < 2; j++) {
            if (relu) {
#pragma unroll
                for (int e = 0; e < acc[i][j].num_elements; e++)
                    acc[i][j].x[e] = fmaxf(acc[i][j].x[e], 0.f);
            }
            const long long off = (long long)(m0 + wm * 64 + i * 16) * ldc + n0 + wn * 32 + j * 16;
            if (C)
                wmma::store_matrix_sync(C + off, acc[i][j], ldc, wmma::mem_row_major);
            if (Cbf)
                frag_to_bf16(&stage[warp][0], acc[i][j], Cbf + off, ldc, lane, 1.f);
        }
}

// =====================================================================
// bf16 WMMA scores (layer 2, NT): bf16 out = 0.125 * Q @ K^T
// =====================================================================
__global__ void __launch_bounds__(256) bscores(
    const bf16* __restrict__ Q, const bf16* __restrict__ Kv, bf16* __restrict__ S)
{
    const int z = blockIdx.z;
    const int b = z >> 3, h = z & 7;
    const bf16* Ab = Q  + ((long long)b * TT) * DD + h * DHH;
    const bf16* Bb = Kv + ((long long)b * TT) * DD + h * DHH;
    bf16* Cb = S + (long long)z * TT * TT;

    const int m0 = blockIdx.y * 128, n0 = blockIdx.x * 128;

    __shared__ __align__(16) bf16 As[128][40];
    __shared__ __align__(16) bf16 Ks[128][40];
    __shared__ __align__(16) float stage[8][264];

    const int tid  = threadIdx.x;
    const int warp = tid >> 5;
    const int lane = tid & 31;
    const int wm   = warp & 1;
    const int wn   = warp >> 1;

    wmma::fragment<wmma::accumulator, 16, 16, 16, float> acc[4][2];
#pragma unroll
    for (int i = 0; i < 4; i++)
#pragma unroll
        for (int j = 0; j < 2; j++)
            wmma::fill_fragment(acc[i][j], 0.f);

    const int arow = tid >> 2, acg = (tid & 3) * 8;

#pragma unroll
    for (int k0 = 0; k0 < DHH; k0 += 32) {
        uint4 a0 = *(const uint4*)(Ab + (long long)(m0 + arow)      * DD + k0 + acg);
        uint4 a1 = *(const uint4*)(Ab + (long long)(m0 + arow + 64) * DD + k0 + acg);
        uint4 b0 = *(const uint4*)(Bb + (long long)(n0 + arow)      * DD + k0 + acg);
        uint4 b1 = *(const uint4*)(Bb + (long long)(n0 + arow + 64) * DD + k0 + acg);
        __syncthreads();
        *(uint4*)&As[arow][acg]      = a0;
        *(uint4*)&As[arow + 64][acg] = a1;
        *(uint4*)&Ks[arow][acg]      = b0;
        *(uint4*)&Ks[arow + 64][acg] = b1;
        __syncthreads();
#pragma unroll
        for (int kk = 0; kk < 32; kk += 16) {
            wmma::fragment<wmma::matrix_a, 16, 16, 16, bf16, wmma::row_major> af[4];
            wmma::fragment<wmma::matrix_b, 16, 16, 16, bf16, wmma::col_major> bfr[2];
#pragma unroll
            for (int i = 0; i < 4; i++)
                wmma::load_matrix_sync(af[i], &As[wm * 64 + i * 16][kk], 40);
#pragma unroll
            for (int j = 0; j < 2; j++)
                wmma::load_matrix_sync(bfr[j], &Ks[wn * 32 + j * 16][kk], 40);
#pragma unroll
            for (int i = 0; i < 4; i++)
#pragma unroll
                for (int j = 0; j < 2; j++)
                    wmma::mma_sync(acc[i][j], af[i], bfr[j], acc[i][j]);
        }
    }

#pragma unroll
    for (int i = 0; i < 4; i++)
#pragma unroll
        for (int j = 0; j < 2; j++) {
            const long long off = (long long)(m0 + wm * 64 + i * 16) * TT + n0 + wn * 32 + j * 16;
            frag_to_bf16(&stage[warp][0], acc[i][j], Cb + off, TT, lane, 0.125f);
        }
}

// =====================================================================
// bf16 WMMA PV -> bf16 ctx. 128x64x32 tile, 8 warps (4M x 2N).
// =====================================================================
__global__ void __launch_bounds__(256) bpv(
    const bf16* __restrict__ P, const bf16* __restrict__ V, bf16* __restrict__ ctx)
{
    const int z = blockIdx.y;
    const int b = z >> 3, h = z & 7;
    const bf16* Ab = P + (long long)z * TT * TT;
    const bf16* Bb = V + ((long long)b * TT) * DD + h * DHH;
    bf16* Cb = ctx + ((long long)b * TT) * DD + h * DHH;

    const int m0 = blockIdx.x * 128;

    __shared__ __align__(16) bf16 As[128][40];
    __shared__ __align__(16) bf16 Bs[32][72];
    __shared__ __align__(16) float stage[8][264];

    const int tid  = threadIdx.x;
    const int warp = tid >> 5;
    const int lane = tid & 31;
    const int wm   = warp & 3;
    const int wn   = warp >> 2;

    wmma::fragment<wmma::accumulator, 16, 16, 16, float> acc[2][2];
#pragma unroll
    for (int i = 0; i < 2; i++)
#pragma unroll
        for (int j = 0; j < 2; j++)
            wmma::fill_fragment(acc[i][j], 0.f);

    const int arow = tid >> 2, acg = (tid & 3) * 8;
    const int brow = tid >> 3, bcg = (tid & 7) * 8;

    for (int k0 = 0; k0 < TT; k0 += 32) {
        uint4 a0 = *(const uint4*)(Ab + (long long)(m0 + arow)      * TT + k0 + acg);
        uint4 a1 = *(const uint4*)(Ab + (long long)(m0 + arow + 64) * TT + k0 + acg);
        uint4 b0 = *(const uint4*)(Bb + (long long)(k0 + brow) * DD + bcg);
        __syncthreads();
        *(uint4*)&As[arow][acg]      = a0;
        *(uint4*)&As[arow + 64][acg] = a1;
        *(uint4*)&Bs[brow][bcg]      = b0;
        __syncthreads();
#pragma unroll
        for (int kk = 0; kk < 32; kk += 16) {
            wmma::fragment<wmma::matrix_a, 16, 16, 16, bf16, wmma::row_major> af[2];
            wmma::fragment<wmma::matrix_b, 16, 16, 16, bf16, wmma::row_major> bfr[2];
#pragma unroll
            for (int i = 0; i < 2; i++)
                wmma::load_matrix_sync(af[i], &As[wm * 32 + i * 16][kk], 40);
#pragma unroll
            for (int j = 0; j < 2; j++)
                wmma::load_matrix_sync(bfr[j], &Bs[kk][wn * 32 + j * 16], 72);
#pragma unroll
            for (int i = 0; i < 2; i++)
#pragma unroll
                for (int j = 0; j < 2; j++)
                    wmma::mma_sync(acc[i][j], af[i], bfr[j], acc[i][j]);
        }
    }

#pragma unroll
    for (int i = 0; i < 2; i++)
#pragma unroll
        for (int j = 0; j < 2; j++) {
            const long long off = (long long)(m0 + wm * 32 + i * 16) * DD + wn * 32 + j * 16;
            frag_to_bf16(&stage[warp][0], acc[i][j], Cb + off, DD, lane, 1.f);
        }
}

// =====================================================================
// FUSED layer-1 softmax + column-sum.
// fp32 scores in -> bf16 probs out + per-column double atomics into wd.
// One block = 16 rows of one (b,h); warp per row (2 rows/warp),
// lane owns columns k = i*32 + lane.
// =====================================================================
__global__ void __launch_bounds__(256) softmax_cs1(
    const float* __restrict__ S, bf16* __restrict__ Pbf, double* __restrict__ wd)
{
    const long long r0 = (long long)blockIdx.x * 16;
    const int b = (int)(r0 >> 13);                 // 8192 rows per batch
    const int warp = threadIdx.x >> 5;
    const int lane = threadIdx.x & 31;

    __shared__ double colsum[TT];

    float part[32];
#pragma unroll
    for (int i = 0; i < 32; i++) part[i] = 0.f;

#pragma unroll
    for (int rr = 0; rr < 2; rr++) {
        const long long r = r0 + warp + rr * 8;
        const float* row = S + r * TT;
        bf16* prow = Pbf + r * TT;
        float v[32];
        float mx = -3.4e38f;
#pragma unroll
        for (int i = 0; i < 32; i++) {
            v[i] = row[i * 32 + lane];
            mx = fmaxf(mx, v[i]);
        }
#pragma unroll
        for (int s = 16; s > 0; s >>= 1) mx = fmaxf(mx, __shfl_xor_sync(0xffffffffu, mx, s));
        float sum = 0.f;
#pragma unroll
        for (int i = 0; i < 32; i++) { v[i] = expf(v[i] - mx); sum += v[i]; }
#pragma unroll
        for (int s = 16; s > 0; s >>= 1) sum += __shfl_xor_sync(0xffffffffu, sum, s);
        const float inv = 1.f / sum;
#pragma unroll
        for (int i = 0; i < 32; i++) {
            float p = v[i] * inv;
            prow[i * 32 + lane] = __float2bfloat16(p);
            part[i] += p;
        }
    }

    for (int i = threadIdx.x; i < TT; i += 256) colsum[i] = 0.0;
    __syncthreads();
#pragma unroll
    for (int i = 0; i < 32; i++)
        atomicAdd(&colsum[i * 32 + lane], (double)part[i]);
    __syncthreads();
    for (int i = threadIdx.x; i < TT; i += 256)
        atomicAdd(&wd[(long long)b * TT + i], colsum[i]);
}

// =====================================================================
// FUSED layer-2 masked softmax + column-sum (bf16 in-place).
// =====================================================================
__global__ void __launch_bounds__(256) softmax_cs2(
    bf16* __restrict__ P, const int* __restrict__ ids, double* __restrict__ wd)
{
    const long long r0 = (long long)blockIdx.x * 16;
    const int b = (int)(r0 >> 13);
    const int warp = threadIdx.x >> 5;
    const int lane = threadIdx.x & 31;
    const int idbase = b * TT;

    __shared__ double colsum[TT];

    const float NEG = __int_as_float(0xff800000);

    float part[32];
#pragma unroll
    for (int i = 0; i < 32; i++) part[i] = 0.f;

#pragma unroll
    for (int rr = 0; rr < 2; rr++) {
        const long long r = r0 + warp + rr * 8;
        const int q = (int)(r & (TT - 1));
        const int qid = ids[idbase + q];
        bf16* row = P + r * TT;
        float v[32];
        float mx = -3.4e38f;
#pragma unroll
        for (int i = 0; i < 32; i++) {
            const int k = i * 32 + lane;
            float x = __bfloat162float(row[k]);
            if (ids[idbase + k] != qid) x = NEG;
            v[i] = x;
            mx = fmaxf(mx, x);
        }
#pragma unroll
        for (int s = 16; s > 0; s >>= 1) mx = fmaxf(mx, __shfl_xor_sync(0xffffffffu, mx, s));
        float sum = 0.f;
#pragma unroll
        for (int i = 0; i < 32; i++) { v[i] = expf(v[i] - mx); sum += v[i]; }
#pragma unroll
        for (int s = 16; s > 0; s >>= 1) sum += __shfl_xor_sync(0xffffffffu, sum, s);
        const float inv = 1.f / sum;
#pragma unroll
        for (int i = 0; i < 32; i++) {
            float p = v[i] * inv;
            row[i * 32 + lane] = __float2bfloat16(p);
            part[i] += p;
        }
    }

    for (int i = threadIdx.x; i < TT; i += 256) colsum[i] = 0.0;
    __syncthreads();
#pragma unroll
    for (int i = 0; i < 32; i++)
        atomicAdd(&colsum[i * 32 + lane], (double)part[i]);
    __syncthreads();
    for (int i = threadIdx.x; i < TT; i += 256)
        atomicAdd(&wd[(long long)b * TT + i], colsum[i]);
}

// zero both double accumulators
__global__ void __launch_bounds__(256) zero_wd(double* __restrict__ a,
                                               double* __restrict__ b)
{
    const int i = blockIdx.x * 256 + threadIdx.x;
    if (i < BB * TT) { a[i] = 0.0; b[i] = 0.0; }
}

// min / max per batch + write float w = (1/H) * wd
__global__ void __launch_bounds__(256) minmax_k(const double* __restrict__ wd,
                                                float* __restrict__ w,
                                                float* __restrict__ mm)
{
    const int b = blockIdx.x, tid = threadIdx.x;
    __shared__ float smn[256], smx[256];
    float mn = 3.4e38f, mx = -3.4e38f;
    for (int t = tid; t < TT; t += 256) {
        float x = (float)(wd[b * TT + t] * 0.125);
        w[b * TT + t] = x;
        mn = fminf(mn, x); mx = fmaxf(mx, x);
    }
    smn[tid] = mn; smx[tid] = mx; __syncthreads();
    for (int s = 128; s > 0; s >>= 1) {
        if (tid < s) { smn[tid] = fminf(smn[tid], smn[tid + s]); smx[tid] = fmaxf(smx[tid], smx[tid + s]); }
        __syncthreads();
    }
    if (tid == 0) { mm[b * 2] = smn[0]; mm[b * 2 + 1] = smx[0]; }
}

__global__ void winscan_k(const float* __restrict__ w, const float* __restrict__ mm,
                          int* __restrict__ ids)
{
    const int b = threadIdx.x;
    if (b >= BB) return;
    const float mn  = mm[b * 2];
    const float den = mm[b * 2 + 1] - mn + 1e-8f;
    const float* wb = w + b * TT;
    int* idb = ids + b * TT;

    bool cur = ((wb[0] - mn) / den) >= 0.5f;
    int start = 0, wid = 0;
    idb[0] = 0;
    for (int t = 1; t < TT; t++) {
        bool wt = ((wb[t] - mn) / den) >= 0.5f;
        if (wt != cur) {
            cur = wt;
            if (start + 1 != t) { start = t; wid++; }
        }
        idb[t] = wid;
    }
}

// wl = softmax over T of (wd * 1/H)
__global__ void __launch_bounds__(256) softmax1d_k(const double* __restrict__ wd,
                                                   float* __restrict__ wl)
{
    const int b = blockIdx.x, tid = threadIdx.x;
    __shared__ float sh[256];
    float v[4];
    float mx = -3.4e38f;
#pragma unroll
    for (int i = 0; i < 4; i++) {
        v[i] = (float)(wd[b * TT + tid + i * 256] * 0.125);
        mx = fmaxf(mx, v[i]);
    }
    sh[tid] = mx; __syncthreads();
    for (int s = 128; s > 0; s >>= 1) { if (tid < s) sh[tid] = fmaxf(sh[tid], sh[tid + s]); __syncthreads(); }
    mx = sh[0]; __syncthreads();
    float e[4], sum = 0.f;
#pragma unroll
    for (int i = 0; i < 4; i++) { e[i] = expf(v[i] - mx); sum += e[i]; }
    sh[tid] = sum; __syncthreads();
    for (int s = 128; s > 0; s >>= 1) { if (tid < s) sh[tid] += sh[tid + s]; __syncthreads(); }
    const float inv = 1.f / sh[0];
#pragma unroll
    for (int i = 0; i < 4; i++) wl[b * TT + tid + i * 256] = e[i] * inv;
}

// in-place LayerNorm over D=512 + optional bf16 dual write
__global__ void __launch_bounds__(256) ln_k(float* __restrict__ X, bf16* __restrict__ Xbf)
{
    const long long r = blockIdx.x;
    float* row = X + r * DD;
    const int tid = threadIdx.x;
    __shared__ float sh[256];

    float x0 = row[tid], x1 = row[tid + 256];
    sh[tid] = x0 + x1; __syncthreads();
    for (int s = 128; s > 0; s >>= 1) { if (tid < s) sh[tid] += sh[tid + s]; __syncthreads(); }
    const float mean = sh[0] * (1.f / DD);
    __syncthreads();

    const float d0 = x0 - mean, d1 = x1 - mean;
    sh[tid] = d0 * d0 + d1 * d1; __syncthreads();
    for (int s = 128; s > 0; s >>= 1) { if (tid < s) sh[tid] += sh[tid + s]; __syncthreads(); }
    const float var = sh[0] * (1.f / DD);
    const float rs = 1.f / sqrtf(var + 1e-5f);
    const float y0 = d0 * rs, y1 = d1 * rs;
    row[tid] = y0;
    row[tid + 256] = y1;
    if (Xbf) {
        Xbf[r * DD + tid]       = __float2bfloat16(y0);
        Xbf[r * DD + tid + 256] = __float2bfloat16(y1);
    }
}

// float -> bf16 conversion
__global__ void __launch_bounds__(256) f2bf_k(const float* __restrict__ src,
                                              bf16* __restrict__ dst, long long n)
{
    const long long i = ((long long)blockIdx.x * 256 + threadIdx.x) * 4;
    if (i >= n) return;
    float4 v = *(const float4*)(src + i);
    __nv_bfloat162 p0, p1;
    p0.x = __float2bfloat16(v.x); p0.y = __float2bfloat16(v.y);
    p1.x = __float2bfloat16(v.z); p1.y = __float2bfloat16(v.w);
    *(__nv_bfloat162*)(dst + i)     = p0;
    *(__nv_bfloat162*)(dst + i + 2) = p1;
}

// out[:, 0:T, :] = 0 ; out[:, T:2T, :] = x   (float4 granularity)
__global__ void __launch_bounds__(256) outinit_k(const float* __restrict__ x,
                                                 float* __restrict__ out)
{
    const long long idx = ((long long)blockIdx.x * 256 + threadIdx.x) * 4;
    const int d = (int)(idx & (DD - 1));
    const long long rb = idx >> 9;
    const int r = (int)(rb & (2 * TT - 1));
    const int b = (int)(rb >> 11);
    if (r < TT)
        *(float4*)(out + idx) = make_float4(0.f, 0.f, 0.f, 0.f);
    else
        *(float4*)(out + idx) = *(const float4*)(x + ((long long)b * TT + (r - TT)) * DD + d);
}

// segmented pooling: grid (BB, 4), 128 threads, d = blockIdx.y*128 + tid
__global__ void __launch_bounds__(128) pool_k(const float* __restrict__ outl,
                                              const float* __restrict__ wl,
                                              const int* __restrict__ ids,
                                              float* __restrict__ out)
{
    const int b = blockIdx.x;
    const int d = blockIdx.y * 128 + threadIdx.x;
    __shared__ int   sids[TT];
    __shared__ float swl[TT];
    for (int t = threadIdx.x; t < TT; t += 128) {
        sids[t] = ids[b * TT + t];
        swl[t]  = wl[b * TT + t];
    }
    __syncthreads();

    const float* xb = outl + (long long)b * TT * DD + d;
    float acc = 0.f;
    for (int t0 = 0; t0 < TT; t0 += 16) {
        float vals[16];
#pragma unroll
        for (int u = 0; u < 16; u++) vals[u] = xb[(long long)(t0 + u) * DD];
#pragma unroll
        for (int u = 0; u < 16; u++) {
            const int t = t0 + u;
            acc = fmaf(vals[u], swl[t], acc);
            const int curid = sids[t];
            const bool flush = (t == TT - 1) || (sids[t + 1] != curid);
            if (flush) {
                out[((long long)b * 2 * TT + curid) * DD + d] = acc;
                acc = 0.f;
            }
        }
    }
}

__global__ void __launch_bounds__(256) mapping_k(const int* __restrict__ ids,
                                                 float* __restrict__ out2)
{
    const long long idx = (long long)blockIdx.x * 256 + threadIdx.x;
    const int j = (int)(idx & (TT - 1));
    const long long wb = idx >> 10;
    const int wrow = (int)(wb & (TT - 1));
    const int b = (int)(wb >> 10);
    out2[idx] = (ids[b * TT + j] == wrow) ? 1.f : 0.f;
}

// =====================================================================
// host
// =====================================================================
extern "C" void kernel_launch(void* const* d_in, const int* in_sizes, int n_in,
                              void* d_out, int out_size)
{
    (void)in_sizes; (void)n_in; (void)out_size;
    const float* x       = (const float*)d_in[0];
    const float* v_qkv_w = (const float*)d_in[1];
    const float* v_out_w = (const float*)d_in[2];
    const float* v_w1    = (const float*)d_in[3];
    const float* v_w2    = (const float*)d_in[4];
    const float* l_qkv_w = (const float*)d_in[5];
    const float* l_out_w = (const float*)d_in[6];
    const float* l_w1    = (const float*)d_in[7];
    const float* l_w2    = (const float*)d_in[8];
    float* out = (float*)d_out;

    float *qkv, *scores, *tmp, *outv, *outl, *w, *mm, *wl;
    double *wd1, *wd2;
    int* ids;
    bf16 *wbf, *xbf, *qkvbf, *probsbf, *ctxbf, *tmpbf, *outvbf, *ffbf;
    cudaGetSymbolAddress((void**)&qkv,    g_qkv);
    cudaGetSymbolAddress((void**)&scores, g_scores);
    cudaGetSymbolAddress((void**)&tmp,    g_tmp);
    cudaGetSymbolAddress((void**)&outv,   g_outv);
    cudaGetSymbolAddress((void**)&outl,   g_outl);
    cudaGetSymbolAddress((void**)&w,      g_w);
    cudaGetSymbolAddress((void**)&wd1,    g_wd1);
    cudaGetSymbolAddress((void**)&wd2,    g_wd2);
    cudaGetSymbolAddress((void**)&mm,     g_mm);
    cudaGetSymbolAddress((void**)&ids,    g_ids);
    cudaGetSymbolAddress((void**)&wl,     g_wl);
    cudaGetSymbolAddress((void**)&wbf,    g_wbf);
    cudaGetSymbolAddress((void**)&xbf,    g_xbf);
    cudaGetSymbolAddress((void**)&qkvbf,  g_qkvbf);
    cudaGetSymbolAddress((void**)&probsbf,g_probsbf);
    cudaGetSymbolAddress((void**)&ctxbf,  g_ctxbf);
    cudaGetSymbolAddress((void**)&tmpbf,  g_tmpbf);
    cudaGetSymbolAddress((void**)&outvbf, g_outvbf);
    cudaGetSymbolAddress((void**)&ffbf,   g_ffbf);

    const dim3 blk(256);
    const long long sQKVw = (long long)DD * DD;
    const long long sQKVc = (long long)BT * DD;

    zero_wd<<<(BB * TT + 255) / 256, blk>>>(wd1, wd2);

    // ---- weight + input conversions (small) ----
    auto cvt = [&](const float* s, bf16* d, long long n) {
        f2bf_k<<<(unsigned)((n + 1023) / 1024), blk>>>(s, d, n);
    };
    cvt(v_qkv_w, wbf + OFF_VQKV, 3LL * DD * DD);
    cvt(v_out_w, wbf + OFF_VOUT, (long long)DD * DD);
    cvt(v_w1,    wbf + OFF_VW1,  (long long)DD * FFD);
    cvt(v_w2,    wbf + OFF_VW2,  (long long)FFD * DD);
    cvt(l_qkv_w, wbf + OFF_LQKV, 3LL * DD * DD);
    cvt(l_out_w, wbf + OFF_LOUT, (long long)DD * DD);
    cvt(l_w1,    wbf + OFF_LW1,  (long long)DD * FFD);
    cvt(l_w2,    wbf + OFF_LW2,  (long long)FFD * DD);
    cvt(x, xbf, sQKVc);

    // ---------------- layer 1 (vanilla) ----------------
    // Q,K in fp32 (threshold-critical, packed f32x2)
    sgemm128<<<dim3(DD / 128, BT / 128, 2), blk>>>(x, DD, 0, v_qkv_w, DD, sQKVw,
                                                   qkv, DD, sQKVc, DD);
    // V in bf16 (bf16-only output)
    bgemm_nn<<<dim3(DD / 128, BT / 128, 1), blk>>>(xbf, DD, 0,
                                                   wbf + OFF_VQKV + 2 * sQKVw, DD, 0,
                                                   nullptr, qkvbf + 2 * sQKVc, DD, 0,
                                                   nullptr, DD, 0);
    attn_scores128<<<dim3(TT / 128, TT / 128, BHH), blk>>>(qkv, qkv + sQKVc, scores);
    softmax_cs1<<<BHH * TT / 16, blk>>>(scores, probsbf, wd1);
    minmax_k<<<BB, blk>>>(wd1, w, mm);
    winscan_k<<<1, 32>>>(w, mm, ids);
    bpv<<<dim3(TT / 128, BHH), blk>>>(probsbf, qkvbf + 2 * sQKVc, ctxbf);
    bgemm_nn<<<dim3(DD / 128, BT / 128, 1), blk>>>(ctxbf, DD, 0, wbf + OFF_VOUT, DD, 0,
                                                   tmp, nullptr, DD, 0, x, DD, 0);
    ln_k<<<BT, blk>>>(tmp, tmpbf);
    bgemm_nn<<<dim3(FFD / 128, BT / 128, 1), blk>>>(tmpbf, DD, 0, wbf + OFF_VW1, FFD, 0,
                                                    nullptr, ffbf, FFD, 0, nullptr, DD, 1);
    bgemm_nn<<<dim3(DD / 128, BT / 128, 1), blk>>>(ffbf, FFD, 0, wbf + OFF_VW2, DD, 0,
                                                   outv, nullptr, DD, 0, tmp, FFD, 0);
    ln_k<<<BT, blk>>>(outv, outvbf);

    // ---------------- layer 2 (windowed, bf16 throughout) ----------------
    bgemm_nn<<<dim3(DD / 128, BT / 128, 3), blk>>>(outvbf, DD, 0, wbf + OFF_LQKV, DD, sQKVw,
                                                   nullptr, qkvbf, DD, sQKVc,
                                                   nullptr, DD, 0);
    bscores<<<dim3(TT / 128, TT / 128, BHH), blk>>>(qkvbf, qkvbf + sQKVc, probsbf);
    softmax_cs2<<<BHH * TT / 16, blk>>>(probsbf, ids, wd2);
    softmax1d_k<<<BB, blk>>>(wd2, wl);
    bpv<<<dim3(TT / 128, BHH), blk>>>(probsbf, qkvbf + 2 * sQKVc, ctxbf);
    bgemm_nn<<<dim3(DD / 128, BT / 128, 1), blk>>>(ctxbf, DD, 0, wbf + OFF_LOUT, DD, 0,
                                                   tmp, nullptr, DD, 0, outv, DD, 0);
    ln_k<<<BT, blk>>>(tmp, tmpbf);
    bgemm_nn<<<dim3(FFD / 128, BT / 128, 1), blk>>>(tmpbf, DD, 0, wbf + OFF_LW1, FFD, 0,
                                                    nullptr, ffbf, FFD, 0, nullptr, DD, 1);
    bgemm_nn<<<dim3(DD / 128, BT / 128, 1), blk>>>(ffbf, FFD, 0, wbf + OFF_LW2, DD, 0,
                                                   outl, nullptr, DD, 0, tmp, FFD, 0);
    ln_k<<<BT, blk>>>(outl, nullptr);

    // ---------------- outputs ----------------
    const long long n1 = (long long)BB * 2 * TT * DD;
    outinit_k<<<(unsigned)(n1 / 1024), blk>>>(x, out);
    pool_k<<<dim3(BB, 4), 128>>>(outl, wl, ids, out);
    mapping_k<<<(unsigned)(((long long)BB * TT * TT) / 256), blk>>>(ids, out + n1);
}